// round 14
// baseline (speedup 1.0000x reference)
#include <cuda_runtime.h>
#include <cuda_fp16.h>
#include <math.h>
#include <stdint.h>

// ---------------- problem constants ----------------
#define Bz   8
#define BS   512
#define Tz   1536          // 3*BS
#define Dz   768
#define Hz   12
#define HDz  64
#define Lz   12
#define Fz   3072          // 4*D
#define NMz  438
#define Mz   (Bz*Tz)       // 12288 rows
#define QKVN 2304          // 3*Dz packed

// ---------------- helpers ----------------
__device__ __forceinline__ uint32_t smem_u32(const void* p) {
    uint32_t a;
    asm("{ .reg .u64 t; cvta.to.shared.u64 t, %1; cvt.u32.u64 %0, t; }" : "=r"(a) : "l"(p));
    return a;
}
__device__ __forceinline__ void ldmx4(uint32_t* r, uint32_t addr) {
    asm volatile("ldmatrix.sync.aligned.m8n8.x4.shared.b16 {%0,%1,%2,%3}, [%4];"
        : "=r"(r[0]), "=r"(r[1]), "=r"(r[2]), "=r"(r[3]) : "r"(addr));
}
__device__ __forceinline__ void ldmx4t(uint32_t* r, uint32_t addr) {
    asm volatile("ldmatrix.sync.aligned.m8n8.x4.trans.shared.b16 {%0,%1,%2,%3}, [%4];"
        : "=r"(r[0]), "=r"(r[1]), "=r"(r[2]), "=r"(r[3]) : "r"(addr));
}
__device__ __forceinline__ void mma16816(float* d, const uint32_t* a,
                                         uint32_t b0, uint32_t b1) {
    asm volatile("mma.sync.aligned.m16n8k16.row.col.f32.f16.f16.f32 "
        "{%0,%1,%2,%3}, {%4,%5,%6,%7}, {%8,%9}, {%0,%1,%2,%3};"
        : "+f"(d[0]), "+f"(d[1]), "+f"(d[2]), "+f"(d[3])
        : "r"(a[0]), "r"(a[1]), "r"(a[2]), "r"(a[3]), "r"(b0), "r"(b1));
}
__device__ __forceinline__ void cp16(uint32_t saddr, const void* gaddr) {
    asm volatile("cp.async.cg.shared.global [%0], [%1], 16;"
        :: "r"(saddr), "l"(gaddr) : "memory");
}
#define CP_COMMIT() asm volatile("cp.async.commit_group;" ::: "memory")
#define CP_WAIT1()  asm volatile("cp.async.wait_group 1;"  ::: "memory")
#define CP_WAIT0()  asm volatile("cp.async.wait_group 0;"  ::: "memory")

__device__ __forceinline__ void splith(float v, __half& h, __half& l) {
    h = __float2half(v);
    l = __float2half(v - __half2float(h));
}
__device__ __forceinline__ uint32_t pack2h(__half a, __half b) {
    __half2 t = __halves2half2(a, b);
    return *(uint32_t*)&t;
}

// ---------------- scratch ----------------
__device__ float g_x [Mz*Dz];
__device__ __half g_h  [Mz*Dz];
__device__ __half g_qkvh[Mz*QKVN]; __device__ __half g_qkvl[Mz*QKVN];
__device__ __half g_yh [Mz*Dz];
__device__ __half g_fh [Mz*Fz];
// transposed split weights [L][N][K]
__device__ __half g_wqkvh[Lz*QKVN*Dz]; __device__ __half g_wqkvl[Lz*QKVN*Dz];
__device__ __half g_wph[Lz*Dz*Dz];     __device__ __half g_wpl[Lz*Dz*Dz];
__device__ __half g_w1h[Lz*Dz*Fz];     __device__ __half g_w1l[Lz*Dz*Fz];
__device__ __half g_w2h[Lz*Dz*Fz];     __device__ __half g_w2l[Lz*Dz*Fz];
__device__ float g_bqkv[Lz*QKVN];

// ---------------- merged weight split+transpose + bias pack ----------------
__global__ void __launch_bounds__(256) wsplit_all_kernel(
    const float* __restrict__ Wq, const float* __restrict__ Wk,
    const float* __restrict__ Wv, const float* __restrict__ Wp,
    const float* __restrict__ W1, const float* __restrict__ W2,
    const float* __restrict__ bq, const float* __restrict__ bk,
    const float* __restrict__ bv, float* __restrict__ bqkv,
    __half* __restrict__ qkvh, __half* __restrict__ qkvl,
    __half* __restrict__ ph, __half* __restrict__ pl,
    __half* __restrict__ f1h, __half* __restrict__ f1l,
    __half* __restrict__ f2h, __half* __restrict__ f2l)
{
    int idx = blockIdx.x, lyr = blockIdx.y;
    if (idx >= 6912) {
        for (int c = threadIdx.x; c < QKVN; c += 256) {
            float v = (c < Dz) ? bq[lyr*Dz + c] : (c < 2*Dz) ? bk[lyr*Dz + c - Dz]
                                                             : bv[lyr*Dz + c - 2*Dz];
            bqkv[lyr*QKVN + c] = v;
        }
        return;
    }
    const float* W; __half *hi, *lo;
    int x, y, K, N, nroff; size_t obase;
    if (idx < 2304) {
        int which = idx / 576, local = idx % 576;
        x = local % 24; y = local / 24; K = Dz; N = Dz;
        if (which < 3) {
            W = (which == 0) ? Wq : (which == 1) ? Wk : Wv;
            hi = qkvh; lo = qkvl;
            obase = (size_t)lyr * QKVN * Dz; nroff = which * Dz;
        } else {
            W = Wp; hi = ph; lo = pl;
            obase = (size_t)lyr * Dz * Dz; nroff = 0;
        }
    } else if (idx < 4608) {
        int local = idx - 2304;
        x = local % 96; y = local / 96; K = Dz; N = Fz;
        W = W1; hi = f1h; lo = f1l;
        obase = (size_t)lyr * Dz * Fz; nroff = 0;
    } else {
        int local = idx - 4608;
        x = local % 24; y = local / 24; K = Fz; N = Dz;
        W = W2; hi = f2h; lo = f2l;
        obase = (size_t)lyr * Dz * Fz; nroff = 0;
    }
    __shared__ float t[32][33];
    const float* Wl = W + (size_t)lyr * K * N;
    int k0 = y * 32, n0 = x * 32;
    int tx = threadIdx.x & 31, ty = threadIdx.x >> 5;
    #pragma unroll
    for (int i = 0; i < 4; ++i)
        t[ty + i*8][tx] = Wl[(size_t)(k0 + ty + i*8) * N + n0 + tx];
    __syncthreads();
    #pragma unroll
    for (int i = 0; i < 4; ++i) {
        int n = ty + i*8;
        float v = t[tx][n];
        __half h, l; splith(v, h, l);
        size_t o = obase + (size_t)(nroff + n0 + n) * K + k0 + tx;
        hi[o] = h; lo[o] = l;
    }
}

// ---------------- embedding ----------------
__global__ void __launch_bounds__(256) embed_kernel(
    const int* __restrict__ idx_up, const int* __restrict__ idx_down,
    const float* __restrict__ cond, const float* __restrict__ teu,
    const float* __restrict__ ted, const float* __restrict__ pos,
    const float* __restrict__ cw, const float* __restrict__ cb,
    float* __restrict__ x)
{
    int row = blockIdx.x;
    int b = row / Tz, i = row % Tz;
    int seg = i >> 9, p = i & 511;
    __shared__ float cs[NMz];
    float o[3];
    if (seg == 0) {
        for (int kk = threadIdx.x; kk < NMz; kk += 256)
            cs[kk] = cond[((size_t)(b*BS + p))*NMz + kk];
        __syncthreads();
        #pragma unroll
        for (int j = 0; j < 3; ++j) {
            int d = threadIdx.x + j*256;
            float acc = cb[d];
            for (int kk = 0; kk < NMz; ++kk)
                acc = fmaf(cs[kk], cw[kk*Dz + d], acc);
            o[j] = acc;
        }
    } else {
        int tok = (seg == 1) ? idx_up[b*BS + p] : idx_down[b*BS + p];
        const float* te = (seg == 1) ? teu : ted;
        #pragma unroll
        for (int j = 0; j < 3; ++j)
            o[j] = te[(size_t)tok*Dz + threadIdx.x + j*256];
    }
    #pragma unroll
    for (int j = 0; j < 3; ++j) {
        int d = threadIdx.x + j*256;
        x[(size_t)row*Dz + d] = o[j] + pos[(size_t)i*Dz + d];
    }
}

// ---------------- layernorm -> fp16 (hi only) ----------------
__global__ void __launch_bounds__(256) ln_kernel(
    const float* __restrict__ x, const float* __restrict__ w,
    const float* __restrict__ bb, __half* __restrict__ oh)
{
    int row = blockIdx.x;
    const float* xr = x + (size_t)row * Dz;
    int t = threadIdx.x, lane = t & 31, wid = t >> 5;
    float a0 = xr[t], a1 = xr[t+256], a2 = xr[t+512];
    float s = a0 + a1 + a2;
    __shared__ float red[8];
    #pragma unroll
    for (int off = 16; off; off >>= 1) s += __shfl_xor_sync(~0u, s, off);
    if (!lane) red[wid] = s;
    __syncthreads();
    s = red[0]+red[1]+red[2]+red[3]+red[4]+red[5]+red[6]+red[7];
    float mean = s * (1.0f/768.0f);
    float d0 = a0-mean, d1 = a1-mean, d2 = a2-mean;
    float sq = d0*d0 + d1*d1 + d2*d2;
    __syncthreads();
    #pragma unroll
    for (int off = 16; off; off >>= 1) sq += __shfl_xor_sync(~0u, sq, off);
    if (!lane) red[wid] = sq;
    __syncthreads();
    sq = red[0]+red[1]+red[2]+red[3]+red[4]+red[5]+red[6]+red[7];
    float rstd = rsqrtf(sq * (1.0f/768.0f) + 1e-5f);
    size_t ro = (size_t)row * Dz;
    oh[ro+t]     = __float2half(d0*rstd*w[t]     + bb[t]);
    oh[ro+t+256] = __float2half(d1*rstd*w[t+256] + bb[t+256]);
    oh[ro+t+512] = __float2half(d2*rstd*w[t+512] + bb[t+512]);
}

// ---------------- fp16x2 GEMM: 128x128 tile, 8 warps (2x4), 3-stage ring ----
// C = Ah*(Bh+Bl)^T.  epi: 0 Cf=D+b ; 1 gelu->Ch ; 2 Cf=D+b+res ; 3 split->Ch(+Cl if col>=Dz)
#define GKC 32
#define AT 8192                    // 128 rows * 64 B
#define STAGE (3*AT)               // A, Bh, Bl = 24576
#define NSTG 3
#define GSMEM (NSTG*STAGE)         // 73728
#define SWC(r, c) (((r) << 6) + ((((c) ^ (((r) & 7) >> 1))) << 4))

__global__ void __launch_bounds__(256, 2) gemm_kernel(
    const __half* __restrict__ Ah,
    const __half* __restrict__ Bh, const __half* __restrict__ Bl,
    const float* __restrict__ bias, const float* __restrict__ res,
    float* __restrict__ Cf, __half* __restrict__ Ch,
    __half* __restrict__ Cl, int K, int N, int epi)
{
    extern __shared__ char smem[];
    uint32_t sb = smem_u32(smem);
    int tid = threadIdx.x, lane = tid & 31, wid = tid >> 5;   // 8 warps
    int wm = wid & 1, wn = wid >> 1;                          // 2(M) x 4(N)
    int row0 = blockIdx.y * 128, col0 = blockIdx.x * 128;

    float acc[4][4][4];
    #pragma unroll
    for (int a = 0; a < 4; ++a)
        #pragma unroll
        for (int b = 0; b < 4; ++b)
            #pragma unroll
            for (int c = 0; c < 4; ++c) acc[a][b][c] = 0.0f;

    int lr = tid >> 2, lc = tid & 3;    // lr 0..63, chunk lc
    int grp = lane >> 3, lrow = lane & 7;
    int T = K / GKC;

    auto load_stage = [&](int stg) {
        uint32_t st = sb + (stg % NSTG) * STAGE;
        int kc0 = stg * GKC;
        const __half* a = Ah + (size_t)(row0 + lr) * K + kc0 + lc * 8;
        cp16(st + SWC(lr,      lc), a);
        cp16(st + SWC(lr + 64, lc), a + (size_t)64 * K);
        const __half* bh = Bh + (size_t)(col0 + lr) * K + kc0 + lc * 8;
        const __half* bl = Bl + (size_t)(col0 + lr) * K + kc0 + lc * 8;
        cp16(st + AT   + SWC(lr,      lc), bh);
        cp16(st + AT   + SWC(lr + 64, lc), bh + (size_t)64 * K);
        cp16(st + 2*AT + SWC(lr,      lc), bl);
        cp16(st + 2*AT + SWC(lr + 64, lc), bl + (size_t)64 * K);
    };

    load_stage(0); CP_COMMIT();
    load_stage(1); CP_COMMIT();

    for (int kt = 0; kt < T; ++kt) {
        CP_WAIT1();
        __syncthreads();
        if (kt + 2 < T) load_stage(kt + 2);
        CP_COMMIT();

        uint32_t As = sb + (kt % NSTG) * STAGE;
        uint32_t Bhs = As + AT, Bls = As + 2*AT;

        #pragma unroll
        for (int ks = 0; ks < 2; ++ks) {
            uint32_t bh_[2][4], bl_[2][4];
            #pragma unroll
            for (int bi = 0; bi < 2; ++bi) {
                int n = wn*32 + bi*16 + (grp >> 1)*8 + lrow;
                int c = ks*2 + (grp & 1);
                uint32_t off = SWC(n, c);
                ldmx4(bh_[bi], Bhs + off);
                ldmx4(bl_[bi], Bls + off);
            }
            #pragma unroll
            for (int mi = 0; mi < 4; ++mi) {
                int r = wm*64 + mi*16 + (grp & 1)*8 + lrow;
                int c = ks*2 + (grp >> 1);
                uint32_t af[4];
                ldmx4(af, As + SWC(r, c));
                #pragma unroll
                for (int nj = 0; nj < 4; ++nj) {
                    uint32_t b0h = bh_[nj>>1][(nj&1)*2], b1h = bh_[nj>>1][(nj&1)*2+1];
                    uint32_t b0l = bl_[nj>>1][(nj&1)*2], b1l = bl_[nj>>1][(nj&1)*2+1];
                    mma16816(acc[mi][nj], af, b0h, b1h);
                    mma16816(acc[mi][nj], af, b0l, b1l);
                }
            }
        }
    }
    __syncthreads();

    #pragma unroll
    for (int mi = 0; mi < 4; ++mi) {
        #pragma unroll
        for (int nj = 0; nj < 4; ++nj) {
            int gr = row0 + wm*64 + mi*16 + (lane >> 2);
            int gc = col0 + wn*32 + nj*8 + (lane & 3)*2;
            float bz0 = bias[gc], bz1 = bias[gc + 1];
            #pragma unroll
            for (int half_ = 0; half_ < 2; ++half_) {
                int r = gr + half_*8;
                float v0 = acc[mi][nj][half_*2]     + bz0;
                float v1 = acc[mi][nj][half_*2 + 1] + bz1;
                size_t off = (size_t)r * N + gc;
                if (epi == 0) {
                    *(float2*)(Cf + off) = make_float2(v0, v1);
                } else if (epi == 2) {
                    float2 rv = *(const float2*)(res + off);
                    *(float2*)(Cf + off) = make_float2(v0 + rv.x, v1 + rv.y);
                } else if (epi == 1) {
                    float g0 = 0.5f*v0*(1.0f + erff(v0*0.70710678118654752f));
                    float g1 = 0.5f*v1*(1.0f + erff(v1*0.70710678118654752f));
                    *(__half2*)(Ch + off) = __halves2half2(__float2half(g0), __float2half(g1));
                } else {
                    __half h0,l0,h1,l1;
                    splith(v0,h0,l0); splith(v1,h1,l1);
                    *(__half2*)(Ch + off) = __halves2half2(h0, h1);
                    if (gc >= Dz)
                        *(__half2*)(Cl + off) = __halves2half2(l0, l1);
                }
            }
        }
    }
}

// ---------------- MMA flash attention (fp16x2), 128-query CTA, 32-key tiles --
// S = Qh*(Kh+Kl)^T ; O = Ph*(Vh+Vl).  8 warps x 16 query rows.
#define SWA(r, c) (((r) << 7) + ((((c) ^ ((r) & 7))) << 4))
#define ASM_Q  0
#define ASM_KV 16384
#define ASM_TOTAL 49152

__global__ void __launch_bounds__(256) attn_kernel(
    const __half* __restrict__ QKVh, const __half* __restrict__ QKVl,
    __half* __restrict__ Yh)
{
    extern __shared__ char sm[];
    uint32_t sb = smem_u32(sm);
    int qt = blockIdx.x, h = blockIdx.y, b = blockIdx.z;
    int i0 = qt * 128;
    int p0 = i0 & 511;
    int tid = threadIdx.x, lane = tid & 31, wm = tid >> 5;   // 8 warps

    int ntseg = (p0 >> 5) + 4;      // 32-key tiles per segment (covers p0+128)
    int NT = 3 * ntseg;
    int qoff = h * HDz, koff = Dz + h * HDz, voff = 2 * Dz + h * HDz;

    {   // stage Q (hi only): 128 rows x 64 cols
        int rr = tid >> 1, cc0 = (tid & 1) * 4;
        const __half* qhp = QKVh + (size_t)(b*Tz + i0 + rr) * QKVN + qoff;
        #pragma unroll
        for (int c = 0; c < 4; ++c)
            cp16(sb + ASM_Q + SWA(rr, cc0 + c), qhp + (cc0 + c) * 8);
    }
    {   // stage KV tile 0 (32 keys): one chunk per thread per sub-tile
        int rr = tid >> 3, ch = tid & 7;
        size_t grow = (size_t)(b*Tz + rr) * QKVN;
        uint32_t tb = sb + ASM_KV;
        cp16(tb +         SWA(rr, ch), QKVh + grow + koff + ch*8);
        cp16(tb + 4096  + SWA(rr, ch), QKVl + grow + koff + ch*8);
        cp16(tb + 8192  + SWA(rr, ch), QKVh + grow + voff + ch*8);
        cp16(tb + 12288 + SWA(rr, ch), QKVl + grow + voff + ch*8);
        CP_COMMIT();
    }

    float m0 = -1e30f, m1 = -1e30f, l0 = 0.0f, l1 = 0.0f;
    float acc[8][4];
    #pragma unroll
    for (int i = 0; i < 8; ++i)
        #pragma unroll
        for (int j = 0; j < 4; ++j) acc[i][j] = 0.0f;

    uint32_t qhf[4][4];
    int qpos0 = p0 + wm*16 + (lane >> 2);
    int kcol2 = (lane & 3) * 2;

    for (int t = 0; t < NT; ++t) {
        int buf = t & 1;
        if (t + 1 < NT) {
            int t1 = t + 1;
            int seg1 = t1 / ntseg, kt1 = t1 % ntseg;
            int rr = tid >> 3, ch = tid & 7;
            size_t grow = (size_t)(b*Tz + seg1*512 + kt1*32 + rr) * QKVN;
            uint32_t tb = sb + ASM_KV + (buf ^ 1) * 16384;
            cp16(tb +         SWA(rr, ch), QKVh + grow + koff + ch*8);
            cp16(tb + 4096  + SWA(rr, ch), QKVl + grow + koff + ch*8);
            cp16(tb + 8192  + SWA(rr, ch), QKVh + grow + voff + ch*8);
            cp16(tb + 12288 + SWA(rr, ch), QKVl + grow + voff + ch*8);
            CP_COMMIT();
            CP_WAIT1();
        } else {
            CP_WAIT0();
        }
        __syncthreads();

        if (t == 0) {
            #pragma unroll
            for (int ks = 0; ks < 4; ++ks) {
                uint32_t qa = sb + ASM_Q + SWA(wm*16 + (lane & 15), ks*2 + (lane >> 4));
                ldmx4(qhf[ks], qa);
            }
        }

        uint32_t kb = sb + ASM_KV + buf * 16384;
        float sc[4][4];
        #pragma unroll
        for (int i = 0; i < 4; ++i)
            #pragma unroll
            for (int j = 0; j < 4; ++j) sc[i][j] = 0.0f;
        #pragma unroll
        for (int ks = 0; ks < 4; ++ks) {
            uint32_t bh_[2][4], bl_[2][4];
            #pragma unroll
            for (int bi = 0; bi < 2; ++bi) {
                int brow = bi*16 + ((lane >> 4) << 3) + (lane & 7);
                int bc   = ks*2 + ((lane >> 3) & 1);
                uint32_t ba = kb + SWA(brow, bc);
                ldmx4(bh_[bi], ba);
                ldmx4(bl_[bi], ba + 4096);
            }
            #pragma unroll
            for (int nt = 0; nt < 4; ++nt) {
                uint32_t b0h = bh_[nt>>1][(nt&1)*2], b1h = bh_[nt>>1][(nt&1)*2+1];
                uint32_t b0l = bl_[nt>>1][(nt&1)*2], b1l = bl_[nt>>1][(nt&1)*2+1];
                mma16816(sc[nt], qhf[ks], b0h, b1h);
                mma16816(sc[nt], qhf[ks], b0l, b1l);
            }
        }
        int kt = t % ntseg;
        int keybase = kt * 32;
        #pragma unroll
        for (int nt = 0; nt < 4; ++nt) {
            #pragma unroll
            for (int c = 0; c < 4; ++c) {
                int kp = keybase + nt*8 + kcol2 + (c & 1);
                int qp = (c < 2) ? qpos0 : qpos0 + 8;
                sc[nt][c] = (kp <= qp) ? sc[nt][c] * 0.125f : -1e30f;
            }
        }
        float smax0 = -1e30f, smax1 = -1e30f;
        #pragma unroll
        for (int nt = 0; nt < 4; ++nt) {
            smax0 = fmaxf(smax0, fmaxf(sc[nt][0], sc[nt][1]));
            smax1 = fmaxf(smax1, fmaxf(sc[nt][2], sc[nt][3]));
        }
        smax0 = fmaxf(smax0, __shfl_xor_sync(~0u, smax0, 1));
        smax0 = fmaxf(smax0, __shfl_xor_sync(~0u, smax0, 2));
        smax1 = fmaxf(smax1, __shfl_xor_sync(~0u, smax1, 1));
        smax1 = fmaxf(smax1, __shfl_xor_sync(~0u, smax1, 2));
        float mn0 = fmaxf(m0, smax0), mn1 = fmaxf(m1, smax1);
        float cr0 = __expf(m0 - mn0), cr1 = __expf(m1 - mn1);
        float p[4][4];
        float ps0 = 0.0f, ps1 = 0.0f;
        #pragma unroll
        for (int nt = 0; nt < 4; ++nt) {
            p[nt][0] = __expf(sc[nt][0] - mn0);
            p[nt][1] = __expf(sc[nt][1] - mn0);
            p[nt][2] = __expf(sc[nt][2] - mn1);
            p[nt][3] = __expf(sc[nt][3] - mn1);
            ps0 += p[nt][0] + p[nt][1];
            ps1 += p[nt][2] + p[nt][3];
        }
        ps0 += __shfl_xor_sync(~0u, ps0, 1);
        ps0 += __shfl_xor_sync(~0u, ps0, 2);
        ps1 += __shfl_xor_sync(~0u, ps1, 1);
        ps1 += __shfl_xor_sync(~0u, ps1, 2);
        l0 = l0 * cr0 + ps0;
        l1 = l1 * cr1 + ps1;
        #pragma unroll
        for (int nt = 0; nt < 8; ++nt) {
            acc[nt][0] *= cr0; acc[nt][1] *= cr0;
            acc[nt][2] *= cr1; acc[nt][3] *= cr1;
        }
        m0 = mn0; m1 = mn1;
        uint32_t pha[2][4];
        #pragma unroll
        for (int ks = 0; ks < 2; ++ks) {
            #pragma unroll
            for (int j = 0; j < 4; ++j) {
                int nt = ks*2 + (j >> 1);
                int c0 = (j & 1) * 2;
                int slot = (j >> 1) * 2 + (j & 1);
                pha[ks][slot] = pack2h(__float2half(p[nt][c0]), __float2half(p[nt][c0+1]));
            }
        }
        uint32_t vb = kb + 8192;
        #pragma unroll
        for (int ks = 0; ks < 2; ++ks) {
            #pragma unroll
            for (int dg = 0; dg < 4; ++dg) {
                int vrow = ks*16 + (lane & 15);
                int vc   = dg*2 + (lane >> 4);
                uint32_t va = vb + SWA(vrow, vc);
                uint32_t vbh_[4], vbl_[4];
                ldmx4t(vbh_, va);
                ldmx4t(vbl_, va + 4096);
                #pragma unroll
                for (int sub = 0; sub < 2; ++sub) {
                    int nt = dg*2 + sub;
                    mma16816(acc[nt], pha[ks], vbh_[sub*2], vbh_[sub*2+1]);
                    mma16816(acc[nt], pha[ks], vbl_[sub*2], vbl_[sub*2+1]);
                }
            }
        }
        __syncthreads();
    }

    float inv0 = 1.0f / l0, inv1 = 1.0f / l1;
    int gr0 = b*Tz + i0 + wm*16 + (lane >> 2);
    #pragma unroll
    for (int nt = 0; nt < 8; ++nt) {
        int col = h*HDz + nt*8 + kcol2;
        size_t o0 = (size_t)gr0 * Dz + col;
        size_t o1 = (size_t)(gr0 + 8) * Dz + col;
        *(__half2*)(Yh + o0) = __halves2half2(__float2half(acc[nt][0]*inv0),
                                              __float2half(acc[nt][1]*inv0));
        *(__half2*)(Yh + o1) = __halves2half2(__float2half(acc[nt][2]*inv1),
                                              __float2half(acc[nt][3]*inv1));
    }
}

// ---------------- launch ----------------
extern "C" void kernel_launch(void* const* d_in, const int* in_sizes, int n_in,
                              void* d_out, int out_size)
{
    const int*   idx_up   = (const int*)  d_in[0];
    const int*   idx_down = (const int*)  d_in[1];
    const float* cond     = (const float*)d_in[2];
    const float* teu      = (const float*)d_in[3];
    const float* ted      = (const float*)d_in[4];
    const float* pos      = (const float*)d_in[5];
    const float* cw       = (const float*)d_in[6];
    const float* cb       = (const float*)d_in[7];
    const float* ln1w     = (const float*)d_in[8];
    const float* ln1b     = (const float*)d_in[9];
    const float* ln2w     = (const float*)d_in[10];
    const float* ln2b     = (const float*)d_in[11];
    const float* Wq       = (const float*)d_in[12];
    const float* bq       = (const float*)d_in[13];
    const float* Wk       = (const float*)d_in[14];
    const float* bk       = (const float*)d_in[15];
    const float* Wv       = (const float*)d_in[16];
    const float* bv       = (const float*)d_in[17];
    const float* Wp       = (const float*)d_in[18];
    const float* bp       = (const float*)d_in[19];
    const float* W1       = (const float*)d_in[20];
    const float* b1       = (const float*)d_in[21];
    const float* W2       = (const float*)d_in[22];
    const float* b2       = (const float*)d_in[23];

    float *x, *bqkv;
    __half *hh, *yh, *fh, *qkvh, *qkvl;
    __half *wqkvh, *wqkvl, *wph, *wpl, *w1h, *w1l, *w2h, *w2l;
    cudaGetSymbolAddress((void**)&x,  g_x);
    cudaGetSymbolAddress((void**)&bqkv, g_bqkv);
    cudaGetSymbolAddress((void**)&hh, g_h);
    cudaGetSymbolAddress((void**)&yh, g_yh);
    cudaGetSymbolAddress((void**)&fh, g_fh);
    cudaGetSymbolAddress((void**)&qkvh, g_qkvh); cudaGetSymbolAddress((void**)&qkvl, g_qkvl);
    cudaGetSymbolAddress((void**)&wqkvh, g_wqkvh); cudaGetSymbolAddress((void**)&wqkvl, g_wqkvl);
    cudaGetSymbolAddress((void**)&wph, g_wph); cudaGetSymbolAddress((void**)&wpl, g_wpl);
    cudaGetSymbolAddress((void**)&w1h, g_w1h); cudaGetSymbolAddress((void**)&w1l, g_w1l);
    cudaGetSymbolAddress((void**)&w2h, g_w2h); cudaGetSymbolAddress((void**)&w2l, g_w2l);

    cudaFuncSetAttribute(gemm_kernel, cudaFuncAttributeMaxDynamicSharedMemorySize, GSMEM);
    cudaFuncSetAttribute(attn_kernel, cudaFuncAttributeMaxDynamicSharedMemorySize, ASM_TOTAL);

    wsplit_all_kernel<<<dim3(6913, Lz), 256>>>(Wq, Wk, Wv, Wp, W1, W2,
        bq, bk, bv, bqkv,
        wqkvh, wqkvl, wph, wpl, w1h, w1l, w2h, w2l);                       // 1
    embed_kernel<<<Mz, 256>>>(idx_up, idx_down, cond, teu, ted, pos, cw, cb, x); // 2

    dim3 gQKV(QKVN/128, Mz/128);   // (18, 96)
    dim3 gD(Dz/128, Mz/128);       // (6, 96)
    dim3 gF(Fz/128, Mz/128);       // (24, 96)
    size_t DD = (size_t)Dz * Dz, DF = (size_t)Dz * Fz, DQ = (size_t)QKVN * Dz;

    for (int l = 0; l < Lz; ++l) {
        ln_kernel<<<Mz, 256>>>(x, ln1w + l*Dz, ln1b + l*Dz, hh);                 // 3
        gemm_kernel<<<gQKV, 256, GSMEM>>>(hh, wqkvh + l*DQ, wqkvl + l*DQ,
            bqkv + l*QKVN, nullptr, nullptr, qkvh, qkvl, Dz, QKVN, 3);           // 4 <- ncu
        attn_kernel<<<dim3(Tz/128, Hz, Bz), 256, ASM_TOTAL>>>(qkvh, qkvl, yh);
        gemm_kernel<<<gD, 256, GSMEM>>>(yh, wph + l*DD, wpl + l*DD,
            bp + l*Dz, x, x, nullptr, nullptr, Dz, Dz, 2);
        ln_kernel<<<Mz, 256>>>(x, ln2w + l*Dz, ln2b + l*Dz, hh);
        gemm_kernel<<<gF, 256, GSMEM>>>(hh, w1h + l*DF, w1l + l*DF,
            b1 + l*Fz, nullptr, nullptr, fh, nullptr, Dz, Fz, 1);
        gemm_kernel<<<gD, 256, GSMEM>>>(fh, w2h + l*DF, w2l + l*DF,
            b2 + l*Dz, x, x, nullptr, nullptr, Fz, Dz, 2);
    }

    cudaMemcpyAsync(d_out, x, (size_t)out_size * sizeof(float),
                    cudaMemcpyDeviceToDevice, 0);
}

// round 15
// speedup vs baseline: 1.0200x; 1.0200x over previous
#include <cuda_runtime.h>
#include <cuda_fp16.h>
#include <math.h>
#include <stdint.h>

// ---------------- problem constants ----------------
#define Bz   8
#define BS   512
#define Tz   1536          // 3*BS
#define Dz   768
#define Hz   12
#define HDz  64
#define Lz   12
#define Fz   3072          // 4*D
#define NMz  438
#define Mz   (Bz*Tz)       // 12288 rows
#define QKVN 2304          // 3*Dz packed

// ---------------- helpers ----------------
__device__ __forceinline__ uint32_t smem_u32(const void* p) {
    uint32_t a;
    asm("{ .reg .u64 t; cvta.to.shared.u64 t, %1; cvt.u32.u64 %0, t; }" : "=r"(a) : "l"(p));
    return a;
}
__device__ __forceinline__ void ldmx4(uint32_t* r, uint32_t addr) {
    asm volatile("ldmatrix.sync.aligned.m8n8.x4.shared.b16 {%0,%1,%2,%3}, [%4];"
        : "=r"(r[0]), "=r"(r[1]), "=r"(r[2]), "=r"(r[3]) : "r"(addr));
}
__device__ __forceinline__ void ldmx4t(uint32_t* r, uint32_t addr) {
    asm volatile("ldmatrix.sync.aligned.m8n8.x4.trans.shared.b16 {%0,%1,%2,%3}, [%4];"
        : "=r"(r[0]), "=r"(r[1]), "=r"(r[2]), "=r"(r[3]) : "r"(addr));
}
__device__ __forceinline__ void mma16816(float* d, const uint32_t* a,
                                         uint32_t b0, uint32_t b1) {
    asm volatile("mma.sync.aligned.m16n8k16.row.col.f32.f16.f16.f32 "
        "{%0,%1,%2,%3}, {%4,%5,%6,%7}, {%8,%9}, {%0,%1,%2,%3};"
        : "+f"(d[0]), "+f"(d[1]), "+f"(d[2]), "+f"(d[3])
        : "r"(a[0]), "r"(a[1]), "r"(a[2]), "r"(a[3]), "r"(b0), "r"(b1));
}
__device__ __forceinline__ void cp16(uint32_t saddr, const void* gaddr) {
    asm volatile("cp.async.cg.shared.global [%0], [%1], 16;"
        :: "r"(saddr), "l"(gaddr) : "memory");
}
#define CP_COMMIT() asm volatile("cp.async.commit_group;" ::: "memory")
#define CP_WAIT1()  asm volatile("cp.async.wait_group 1;"  ::: "memory")
#define CP_WAIT0()  asm volatile("cp.async.wait_group 0;"  ::: "memory")

__device__ __forceinline__ void splith(float v, __half& h, __half& l) {
    h = __float2half(v);
    l = __float2half(v - __half2float(h));
}
__device__ __forceinline__ uint32_t pack2h(__half a, __half b) {
    __half2 t = __halves2half2(a, b);
    return *(uint32_t*)&t;
}

// ---------------- scratch ----------------
__device__ float g_x [Mz*Dz];
__device__ __half g_h  [Mz*Dz];
__device__ __half g_qkvh[Mz*QKVN]; __device__ __half g_qkvl[Mz*QKVN];
__device__ __half g_yh [Mz*Dz];
__device__ __half g_fh [Mz*Fz];
// transposed split weights [L][N][K]
__device__ __half g_wqkvh[Lz*QKVN*Dz]; __device__ __half g_wqkvl[Lz*QKVN*Dz];
__device__ __half g_wph[Lz*Dz*Dz];     __device__ __half g_wpl[Lz*Dz*Dz];
__device__ __half g_w1h[Lz*Dz*Fz];     __device__ __half g_w1l[Lz*Dz*Fz];
__device__ __half g_w2h[Lz*Dz*Fz];     __device__ __half g_w2l[Lz*Dz*Fz];
__device__ float g_bqkv[Lz*QKVN];

// ---------------- merged weight split+transpose + bias pack ----------------
__global__ void __launch_bounds__(256) wsplit_all_kernel(
    const float* __restrict__ Wq, const float* __restrict__ Wk,
    const float* __restrict__ Wv, const float* __restrict__ Wp,
    const float* __restrict__ W1, const float* __restrict__ W2,
    const float* __restrict__ bq, const float* __restrict__ bk,
    const float* __restrict__ bv, float* __restrict__ bqkv,
    __half* __restrict__ qkvh, __half* __restrict__ qkvl,
    __half* __restrict__ ph, __half* __restrict__ pl,
    __half* __restrict__ f1h, __half* __restrict__ f1l,
    __half* __restrict__ f2h, __half* __restrict__ f2l)
{
    int idx = blockIdx.x, lyr = blockIdx.y;
    if (idx >= 6912) {
        for (int c = threadIdx.x; c < QKVN; c += 256) {
            float v = (c < Dz) ? bq[lyr*Dz + c] : (c < 2*Dz) ? bk[lyr*Dz + c - Dz]
                                                             : bv[lyr*Dz + c - 2*Dz];
            bqkv[lyr*QKVN + c] = v;
        }
        return;
    }
    const float* W; __half *hi, *lo;
    int x, y, K, N, nroff; size_t obase;
    if (idx < 2304) {
        int which = idx / 576, local = idx % 576;
        x = local % 24; y = local / 24; K = Dz; N = Dz;
        if (which < 3) {
            W = (which == 0) ? Wq : (which == 1) ? Wk : Wv;
            hi = qkvh; lo = qkvl;
            obase = (size_t)lyr * QKVN * Dz; nroff = which * Dz;
        } else {
            W = Wp; hi = ph; lo = pl;
            obase = (size_t)lyr * Dz * Dz; nroff = 0;
        }
    } else if (idx < 4608) {
        int local = idx - 2304;
        x = local % 96; y = local / 96; K = Dz; N = Fz;
        W = W1; hi = f1h; lo = f1l;
        obase = (size_t)lyr * Dz * Fz; nroff = 0;
    } else {
        int local = idx - 4608;
        x = local % 24; y = local / 24; K = Fz; N = Dz;
        W = W2; hi = f2h; lo = f2l;
        obase = (size_t)lyr * Dz * Fz; nroff = 0;
    }
    __shared__ float t[32][33];
    const float* Wl = W + (size_t)lyr * K * N;
    int k0 = y * 32, n0 = x * 32;
    int tx = threadIdx.x & 31, ty = threadIdx.x >> 5;
    #pragma unroll
    for (int i = 0; i < 4; ++i)
        t[ty + i*8][tx] = Wl[(size_t)(k0 + ty + i*8) * N + n0 + tx];
    __syncthreads();
    #pragma unroll
    for (int i = 0; i < 4; ++i) {
        int n = ty + i*8;
        float v = t[tx][n];
        __half h, l; splith(v, h, l);
        size_t o = obase + (size_t)(nroff + n0 + n) * K + k0 + tx;
        hi[o] = h; lo[o] = l;
    }
}

// ---------------- embedding ----------------
__global__ void __launch_bounds__(256) embed_kernel(
    const int* __restrict__ idx_up, const int* __restrict__ idx_down,
    const float* __restrict__ cond, const float* __restrict__ teu,
    const float* __restrict__ ted, const float* __restrict__ pos,
    const float* __restrict__ cw, const float* __restrict__ cb,
    float* __restrict__ x)
{
    int row = blockIdx.x;
    int b = row / Tz, i = row % Tz;
    int seg = i >> 9, p = i & 511;
    __shared__ float cs[NMz];
    float o[3];
    if (seg == 0) {
        for (int kk = threadIdx.x; kk < NMz; kk += 256)
            cs[kk] = cond[((size_t)(b*BS + p))*NMz + kk];
        __syncthreads();
        #pragma unroll
        for (int j = 0; j < 3; ++j) {
            int d = threadIdx.x + j*256;
            float acc = cb[d];
            for (int kk = 0; kk < NMz; ++kk)
                acc = fmaf(cs[kk], cw[kk*Dz + d], acc);
            o[j] = acc;
        }
    } else {
        int tok = (seg == 1) ? idx_up[b*BS + p] : idx_down[b*BS + p];
        const float* te = (seg == 1) ? teu : ted;
        #pragma unroll
        for (int j = 0; j < 3; ++j)
            o[j] = te[(size_t)tok*Dz + threadIdx.x + j*256];
    }
    #pragma unroll
    for (int j = 0; j < 3; ++j) {
        int d = threadIdx.x + j*256;
        x[(size_t)row*Dz + d] = o[j] + pos[(size_t)i*Dz + d];
    }
}

// ---------------- layernorm -> fp16 (hi only) ----------------
__global__ void __launch_bounds__(256) ln_kernel(
    const float* __restrict__ x, const float* __restrict__ w,
    const float* __restrict__ bb, __half* __restrict__ oh)
{
    int row = blockIdx.x;
    const float* xr = x + (size_t)row * Dz;
    int t = threadIdx.x, lane = t & 31, wid = t >> 5;
    float a0 = xr[t], a1 = xr[t+256], a2 = xr[t+512];
    float s = a0 + a1 + a2;
    __shared__ float red[8];
    #pragma unroll
    for (int off = 16; off; off >>= 1) s += __shfl_xor_sync(~0u, s, off);
    if (!lane) red[wid] = s;
    __syncthreads();
    s = red[0]+red[1]+red[2]+red[3]+red[4]+red[5]+red[6]+red[7];
    float mean = s * (1.0f/768.0f);
    float d0 = a0-mean, d1 = a1-mean, d2 = a2-mean;
    float sq = d0*d0 + d1*d1 + d2*d2;
    __syncthreads();
    #pragma unroll
    for (int off = 16; off; off >>= 1) sq += __shfl_xor_sync(~0u, sq, off);
    if (!lane) red[wid] = sq;
    __syncthreads();
    sq = red[0]+red[1]+red[2]+red[3]+red[4]+red[5]+red[6]+red[7];
    float rstd = rsqrtf(sq * (1.0f/768.0f) + 1e-5f);
    size_t ro = (size_t)row * Dz;
    oh[ro+t]     = __float2half(d0*rstd*w[t]     + bb[t]);
    oh[ro+t+256] = __float2half(d1*rstd*w[t+256] + bb[t+256]);
    oh[ro+t+512] = __float2half(d2*rstd*w[t+512] + bb[t+512]);
}

// ---------------- fp16x2 GEMM: 128x128 tile, 8 warps (2x4), 4-stage ring ----
// C = Ah*(Bh+Bl)^T.  epi: 0 Cf=D+b ; 1 gelu->Ch ; 2 Cf=D+b+res ; 3 split->Ch(+Cl if col>=Dz)
#define GKC 32
#define AT 8192                    // 128 rows * 64 B
#define STAGE (3*AT)               // A, Bh, Bl = 24576
#define NSTG 4
#define GSMEM (NSTG*STAGE)         // 98304
#define SWC(r, c) (((r) << 6) + ((((c) ^ (((r) & 7) >> 1))) << 4))

__global__ void __launch_bounds__(256, 2) gemm_kernel(
    const __half* __restrict__ Ah,
    const __half* __restrict__ Bh, const __half* __restrict__ Bl,
    const float* __restrict__ bias, const float* __restrict__ res,
    float* __restrict__ Cf, __half* __restrict__ Ch,
    __half* __restrict__ Cl, int K, int N, int epi)
{
    extern __shared__ char smem[];
    uint32_t sb = smem_u32(smem);
    int tid = threadIdx.x, lane = tid & 31, wid = tid >> 5;   // 8 warps
    int wm = wid & 1, wn = wid >> 1;                          // 2(M) x 4(N)
    int row0 = blockIdx.y * 128, col0 = blockIdx.x * 128;

    float acc[4][4][4];
    #pragma unroll
    for (int a = 0; a < 4; ++a)
        #pragma unroll
        for (int b = 0; b < 4; ++b)
            #pragma unroll
            for (int c = 0; c < 4; ++c) acc[a][b][c] = 0.0f;

    int lr = tid >> 2, lc = tid & 3;    // lr 0..63, chunk lc
    int grp = lane >> 3, lrow = lane & 7;
    int T = K / GKC;

    auto load_stage = [&](int stg) {
        uint32_t st = sb + (stg % NSTG) * STAGE;
        int kc0 = stg * GKC;
        const __half* a = Ah + (size_t)(row0 + lr) * K + kc0 + lc * 8;
        cp16(st + SWC(lr,      lc), a);
        cp16(st + SWC(lr + 64, lc), a + (size_t)64 * K);
        const __half* bh = Bh + (size_t)(col0 + lr) * K + kc0 + lc * 8;
        const __half* bl = Bl + (size_t)(col0 + lr) * K + kc0 + lc * 8;
        cp16(st + AT   + SWC(lr,      lc), bh);
        cp16(st + AT   + SWC(lr + 64, lc), bh + (size_t)64 * K);
        cp16(st + 2*AT + SWC(lr,      lc), bl);
        cp16(st + 2*AT + SWC(lr + 64, lc), bl + (size_t)64 * K);
    };

    load_stage(0); CP_COMMIT();
    load_stage(1); CP_COMMIT();

    for (int kt = 0; kt < T; ++kt) {
        CP_WAIT1();
        __syncthreads();
        if (kt + 2 < T) load_stage(kt + 2);
        CP_COMMIT();

        uint32_t As = sb + (kt % NSTG) * STAGE;
        uint32_t Bhs = As + AT, Bls = As + 2*AT;

        #pragma unroll
        for (int ks = 0; ks < 2; ++ks) {
            uint32_t bh_[2][4], bl_[2][4];
            #pragma unroll
            for (int bi = 0; bi < 2; ++bi) {
                int n = wn*32 + bi*16 + (grp >> 1)*8 + lrow;
                int c = ks*2 + (grp & 1);
                uint32_t off = SWC(n, c);
                ldmx4(bh_[bi], Bhs + off);
                ldmx4(bl_[bi], Bls + off);
            }
            #pragma unroll
            for (int mi = 0; mi < 4; ++mi) {
                int r = wm*64 + mi*16 + (grp & 1)*8 + lrow;
                int c = ks*2 + (grp >> 1);
                uint32_t af[4];
                ldmx4(af, As + SWC(r, c));
                #pragma unroll
                for (int nj = 0; nj < 4; ++nj) {
                    uint32_t b0h = bh_[nj>>1][(nj&1)*2], b1h = bh_[nj>>1][(nj&1)*2+1];
                    uint32_t b0l = bl_[nj>>1][(nj&1)*2], b1l = bl_[nj>>1][(nj&1)*2+1];
                    mma16816(acc[mi][nj], af, b0h, b1h);
                    mma16816(acc[mi][nj], af, b0l, b1l);
                }
            }
        }
    }
    __syncthreads();

    #pragma unroll
    for (int mi = 0; mi < 4; ++mi) {
        #pragma unroll
        for (int nj = 0; nj < 4; ++nj) {
            int gr = row0 + wm*64 + mi*16 + (lane >> 2);
            int gc = col0 + wn*32 + nj*8 + (lane & 3)*2;
            float bz0 = bias[gc], bz1 = bias[gc + 1];
            #pragma unroll
            for (int half_ = 0; half_ < 2; ++half_) {
                int r = gr + half_*8;
                float v0 = acc[mi][nj][half_*2]     + bz0;
                float v1 = acc[mi][nj][half_*2 + 1] + bz1;
                size_t off = (size_t)r * N + gc;
                if (epi == 0) {
                    *(float2*)(Cf + off) = make_float2(v0, v1);
                } else if (epi == 2) {
                    float2 rv = *(const float2*)(res + off);
                    *(float2*)(Cf + off) = make_float2(v0 + rv.x, v1 + rv.y);
                } else if (epi == 1) {
                    float g0 = 0.5f*v0*(1.0f + erff(v0*0.70710678118654752f));
                    float g1 = 0.5f*v1*(1.0f + erff(v1*0.70710678118654752f));
                    *(__half2*)(Ch + off) = __halves2half2(__float2half(g0), __float2half(g1));
                } else {
                    __half h0,l0,h1,l1;
                    splith(v0,h0,l0); splith(v1,h1,l1);
                    *(__half2*)(Ch + off) = __halves2half2(h0, h1);
                    if (gc >= Dz)
                        *(__half2*)(Cl + off) = __halves2half2(l0, l1);
                }
            }
        }
    }
}

// ---------------- MMA flash attention (fp16x2), 64-query CTA, 32-key tiles --
// S = Qh*(Kh+Kl)^T ; O = Ph*(Vh+Vl)   [R13 measured-best shape]
#define SWA(r, c) (((r) << 7) + ((((c) ^ ((r) & 7))) << 4))
#define ASM_Q  0
#define ASM_KV 8192
#define ASM_TOTAL 40960

__global__ void __launch_bounds__(128) attn_kernel(
    const __half* __restrict__ QKVh, const __half* __restrict__ QKVl,
    __half* __restrict__ Yh)
{
    extern __shared__ char sm[];
    uint32_t sb = smem_u32(sm);
    int qt = blockIdx.x, h = blockIdx.y, b = blockIdx.z;
    int i0 = qt * 64;
    int p0 = i0 & 511;
    int tid = threadIdx.x, lane = tid & 31, wm = tid >> 5;

    int ntseg = (p0 >> 5) + 2;
    int NT = 3 * ntseg;
    int qoff = h * HDz, koff = Dz + h * HDz, voff = 2 * Dz + h * HDz;

    {   // stage Q (hi only)
        int rr = tid >> 1, cc0 = (tid & 1) * 4;
        const __half* qhp = QKVh + (size_t)(b*Tz + i0 + rr) * QKVN + qoff;
        #pragma unroll
        for (int c = 0; c < 4; ++c)
            cp16(sb + ASM_Q + SWA(rr, cc0 + c), qhp + (cc0 + c) * 8);
    }
    {   // stage KV tile 0
        int rr = tid >> 2, cc0 = (tid & 3) * 2;
        size_t grow = (size_t)(b*Tz + rr) * QKVN;
        uint32_t tb = sb + ASM_KV;
        #pragma unroll
        for (int c = 0; c < 2; ++c) {
            int ch = cc0 + c;
            cp16(tb +         SWA(rr, ch), QKVh + grow + koff + ch*8);
            cp16(tb + 4096  + SWA(rr, ch), QKVl + grow + koff + ch*8);
            cp16(tb + 8192  + SWA(rr, ch), QKVh + grow + voff + ch*8);
            cp16(tb + 12288 + SWA(rr, ch), QKVl + grow + voff + ch*8);
        }
        CP_COMMIT();
    }

    float m0 = -1e30f, m1 = -1e30f, l0 = 0.0f, l1 = 0.0f;
    float acc[8][4];
    #pragma unroll
    for (int i = 0; i < 8; ++i)
        #pragma unroll
        for (int j = 0; j < 4; ++j) acc[i][j] = 0.0f;

    uint32_t qhf[4][4];
    int qpos0 = p0 + wm*16 + (lane >> 2);
    int kcol2 = (lane & 3) * 2;

    for (int t = 0; t < NT; ++t) {
        int buf = t & 1;
        if (t + 1 < NT) {
            int t1 = t + 1;
            int seg1 = t1 / ntseg, kt1 = t1 % ntseg;
            int rr = tid >> 2, cc0 = (tid & 3) * 2;
            size_t grow = (size_t)(b*Tz + seg1*512 + kt1*32 + rr) * QKVN;
            uint32_t tb = sb + ASM_KV + (buf ^ 1) * 16384;
            #pragma unroll
            for (int c = 0; c < 2; ++c) {
                int ch = cc0 + c;
                cp16(tb +         SWA(rr, ch), QKVh + grow + koff + ch*8);
                cp16(tb + 4096  + SWA(rr, ch), QKVl + grow + koff + ch*8);
                cp16(tb + 8192  + SWA(rr, ch), QKVh + grow + voff + ch*8);
                cp16(tb + 12288 + SWA(rr, ch), QKVl + grow + voff + ch*8);
            }
            CP_COMMIT();
            CP_WAIT1();
        } else {
            CP_WAIT0();
        }
        __syncthreads();

        if (t == 0) {
            #pragma unroll
            for (int ks = 0; ks < 4; ++ks) {
                uint32_t qa = sb + ASM_Q + SWA(wm*16 + (lane & 15), ks*2 + (lane >> 4));
                ldmx4(qhf[ks], qa);
            }
        }

        uint32_t kb = sb + ASM_KV + buf * 16384;
        float sc[4][4];
        #pragma unroll
        for (int i = 0; i < 4; ++i)
            #pragma unroll
            for (int j = 0; j < 4; ++j) sc[i][j] = 0.0f;
        #pragma unroll
        for (int ks = 0; ks < 4; ++ks) {
            uint32_t bh_[2][4], bl_[2][4];
            #pragma unroll
            for (int bi = 0; bi < 2; ++bi) {
                int brow = bi*16 + ((lane >> 4) << 3) + (lane & 7);
                int bc   = ks*2 + ((lane >> 3) & 1);
                uint32_t ba = kb + SWA(brow, bc);
                ldmx4(bh_[bi], ba);
                ldmx4(bl_[bi], ba + 4096);
            }
            #pragma unroll
            for (int nt = 0; nt < 4; ++nt) {
                uint32_t b0h = bh_[nt>>1][(nt&1)*2], b1h = bh_[nt>>1][(nt&1)*2+1];
                uint32_t b0l = bl_[nt>>1][(nt&1)*2], b1l = bl_[nt>>1][(nt&1)*2+1];
                mma16816(sc[nt], qhf[ks], b0h, b1h);
                mma16816(sc[nt], qhf[ks], b0l, b1l);
            }
        }
        int kt = t % ntseg;
        int keybase = kt * 32;
        #pragma unroll
        for (int nt = 0; nt < 4; ++nt) {
            #pragma unroll
            for (int c = 0; c < 4; ++c) {
                int kp = keybase + nt*8 + kcol2 + (c & 1);
                int qp = (c < 2) ? qpos0 : qpos0 + 8;
                sc[nt][c] = (kp <= qp) ? sc[nt][c] * 0.125f : -1e30f;
            }
        }
        float smax0 = -1e30f, smax1 = -1e30f;
        #pragma unroll
        for (int nt = 0; nt < 4; ++nt) {
            smax0 = fmaxf(smax0, fmaxf(sc[nt][0], sc[nt][1]));
            smax1 = fmaxf(smax1, fmaxf(sc[nt][2], sc[nt][3]));
        }
        smax0 = fmaxf(smax0, __shfl_xor_sync(~0u, smax0, 1));
        smax0 = fmaxf(smax0, __shfl_xor_sync(~0u, smax0, 2));
        smax1 = fmaxf(smax1, __shfl_xor_sync(~0u, smax1, 1));
        smax1 = fmaxf(smax1, __shfl_xor_sync(~0u, smax1, 2));
        float mn0 = fmaxf(m0, smax0), mn1 = fmaxf(m1, smax1);
        float cr0 = __expf(m0 - mn0), cr1 = __expf(m1 - mn1);
        float p[4][4];
        float ps0 = 0.0f, ps1 = 0.0f;
        #pragma unroll
        for (int nt = 0; nt < 4; ++nt) {
            p[nt][0] = __expf(sc[nt][0] - mn0);
            p[nt][1] = __expf(sc[nt][1] - mn0);
            p[nt][2] = __expf(sc[nt][2] - mn1);
            p[nt][3] = __expf(sc[nt][3] - mn1);
            ps0 += p[nt][0] + p[nt][1];
            ps1 += p[nt][2] + p[nt][3];
        }
        ps0 += __shfl_xor_sync(~0u, ps0, 1);
        ps0 += __shfl_xor_sync(~0u, ps0, 2);
        ps1 += __shfl_xor_sync(~0u, ps1, 1);
        ps1 += __shfl_xor_sync(~0u, ps1, 2);
        l0 = l0 * cr0 + ps0;
        l1 = l1 * cr1 + ps1;
        #pragma unroll
        for (int nt = 0; nt < 8; ++nt) {
            acc[nt][0] *= cr0; acc[nt][1] *= cr0;
            acc[nt][2] *= cr1; acc[nt][3] *= cr1;
        }
        m0 = mn0; m1 = mn1;
        uint32_t pha[2][4];
        #pragma unroll
        for (int ks = 0; ks < 2; ++ks) {
            #pragma unroll
            for (int j = 0; j < 4; ++j) {
                int nt = ks*2 + (j >> 1);
                int c0 = (j & 1) * 2;
                int slot = (j >> 1) * 2 + (j & 1);
                pha[ks][slot] = pack2h(__float2half(p[nt][c0]), __float2half(p[nt][c0+1]));
            }
        }
        uint32_t vb = kb + 8192;
        #pragma unroll
        for (int ks = 0; ks < 2; ++ks) {
            #pragma unroll
            for (int dg = 0; dg < 4; ++dg) {
                int vrow = ks*16 + (lane & 15);
                int vc   = dg*2 + (lane >> 4);
                uint32_t va = vb + SWA(vrow, vc);
                uint32_t vbh_[4], vbl_[4];
                ldmx4t(vbh_, va);
                ldmx4t(vbl_, va + 4096);
                #pragma unroll
                for (int sub = 0; sub < 2; ++sub) {
                    int nt = dg*2 + sub;
                    mma16816(acc[nt], pha[ks], vbh_[sub*2], vbh_[sub*2+1]);
                    mma16816(acc[nt], pha[ks], vbl_[sub*2], vbl_[sub*2+1]);
                }
            }
        }
        __syncthreads();
    }

    float inv0 = 1.0f / l0, inv1 = 1.0f / l1;
    int gr0 = b*Tz + i0 + wm*16 + (lane >> 2);
    #pragma unroll
    for (int nt = 0; nt < 8; ++nt) {
        int col = h*HDz + nt*8 + kcol2;
        size_t o0 = (size_t)gr0 * Dz + col;
        size_t o1 = (size_t)(gr0 + 8) * Dz + col;
        *(__half2*)(Yh + o0) = __halves2half2(__float2half(acc[nt][0]*inv0),
                                              __float2half(acc[nt][1]*inv0));
        *(__half2*)(Yh + o1) = __halves2half2(__float2half(acc[nt][2]*inv1),
                                              __float2half(acc[nt][3]*inv1));
    }
}

// ---------------- launch ----------------
extern "C" void kernel_launch(void* const* d_in, const int* in_sizes, int n_in,
                              void* d_out, int out_size)
{
    const int*   idx_up   = (const int*)  d_in[0];
    const int*   idx_down = (const int*)  d_in[1];
    const float* cond     = (const float*)d_in[2];
    const float* teu      = (const float*)d_in[3];
    const float* ted      = (const float*)d_in[4];
    const float* pos      = (const float*)d_in[5];
    const float* cw       = (const float*)d_in[6];
    const float* cb       = (const float*)d_in[7];
    const float* ln1w     = (const float*)d_in[8];
    const float* ln1b     = (const float*)d_in[9];
    const float* ln2w     = (const float*)d_in[10];
    const float* ln2b     = (const float*)d_in[11];
    const float* Wq       = (const float*)d_in[12];
    const float* bq       = (const float*)d_in[13];
    const float* Wk       = (const float*)d_in[14];
    const float* bk       = (const float*)d_in[15];
    const float* Wv       = (const float*)d_in[16];
    const float* bv       = (const float*)d_in[17];
    const float* Wp       = (const float*)d_in[18];
    const float* bp       = (const float*)d_in[19];
    const float* W1       = (const float*)d_in[20];
    const float* b1       = (const float*)d_in[21];
    const float* W2       = (const float*)d_in[22];
    const float* b2       = (const float*)d_in[23];

    float *x, *bqkv;
    __half *hh, *yh, *fh, *qkvh, *qkvl;
    __half *wqkvh, *wqkvl, *wph, *wpl, *w1h, *w1l, *w2h, *w2l;
    cudaGetSymbolAddress((void**)&x,  g_x);
    cudaGetSymbolAddress((void**)&bqkv, g_bqkv);
    cudaGetSymbolAddress((void**)&hh, g_h);
    cudaGetSymbolAddress((void**)&yh, g_yh);
    cudaGetSymbolAddress((void**)&fh, g_fh);
    cudaGetSymbolAddress((void**)&qkvh, g_qkvh); cudaGetSymbolAddress((void**)&qkvl, g_qkvl);
    cudaGetSymbolAddress((void**)&wqkvh, g_wqkvh); cudaGetSymbolAddress((void**)&wqkvl, g_wqkvl);
    cudaGetSymbolAddress((void**)&wph, g_wph); cudaGetSymbolAddress((void**)&wpl, g_wpl);
    cudaGetSymbolAddress((void**)&w1h, g_w1h); cudaGetSymbolAddress((void**)&w1l, g_w1l);
    cudaGetSymbolAddress((void**)&w2h, g_w2h); cudaGetSymbolAddress((void**)&w2l, g_w2l);

    cudaFuncSetAttribute(gemm_kernel, cudaFuncAttributeMaxDynamicSharedMemorySize, GSMEM);
    cudaFuncSetAttribute(attn_kernel, cudaFuncAttributeMaxDynamicSharedMemorySize, ASM_TOTAL);

    wsplit_all_kernel<<<dim3(6913, Lz), 256>>>(Wq, Wk, Wv, Wp, W1, W2,
        bq, bk, bv, bqkv,
        wqkvh, wqkvl, wph, wpl, w1h, w1l, w2h, w2l);                       // 1
    embed_kernel<<<Mz, 256>>>(idx_up, idx_down, cond, teu, ted, pos, cw, cb, x); // 2

    dim3 gQKV(QKVN/128, Mz/128);   // (18, 96)
    dim3 gD(Dz/128, Mz/128);       // (6, 96)
    dim3 gF(Fz/128, Mz/128);       // (24, 96)
    size_t DD = (size_t)Dz * Dz, DF = (size_t)Dz * Fz, DQ = (size_t)QKVN * Dz;

    for (int l = 0; l < Lz; ++l) {
        ln_kernel<<<Mz, 256>>>(x, ln1w + l*Dz, ln1b + l*Dz, hh);                 // 3
        gemm_kernel<<<gQKV, 256, GSMEM>>>(hh, wqkvh + l*DQ, wqkvl + l*DQ,
            bqkv + l*QKVN, nullptr, nullptr, qkvh, qkvl, Dz, QKVN, 3);           // 4 <- ncu
        attn_kernel<<<dim3(24, Hz, Bz), 128, ASM_TOTAL>>>(qkvh, qkvl, yh);
        gemm_kernel<<<gD, 256, GSMEM>>>(yh, wph + l*DD, wpl + l*DD,
            bp + l*Dz, x, x, nullptr, nullptr, Dz, Dz, 2);
        ln_kernel<<<Mz, 256>>>(x, ln2w + l*Dz, ln2b + l*Dz, hh);
        gemm_kernel<<<gF, 256, GSMEM>>>(hh, w1h + l*DF, w1l + l*DF,
            b1 + l*Fz, nullptr, nullptr, fh, nullptr, Dz, Fz, 1);
        gemm_kernel<<<gD, 256, GSMEM>>>(fh, w2h + l*DF, w2l + l*DF,
            b2 + l*Dz, x, x, nullptr, nullptr, Fz, Dz, 2);
    }

    cudaMemcpyAsync(d_out, x, (size_t)out_size * sizeof(float),
                    cudaMemcpyDeviceToDevice, 0);
}

// round 16
// speedup vs baseline: 1.0419x; 1.0215x over previous
#include <cuda_runtime.h>
#include <cuda_fp16.h>
#include <math.h>
#include <stdint.h>

// ---------------- problem constants ----------------
#define Bz   8
#define BS   512
#define Tz   1536          // 3*BS
#define Dz   768
#define Hz   12
#define HDz  64
#define Lz   12
#define Fz   3072          // 4*D
#define NMz  438
#define Mz   (Bz*Tz)       // 12288 rows
#define QKVN 2304          // 3*Dz packed

// ---------------- helpers ----------------
__device__ __forceinline__ uint32_t smem_u32(const void* p) {
    uint32_t a;
    asm("{ .reg .u64 t; cvta.to.shared.u64 t, %1; cvt.u32.u64 %0, t; }" : "=r"(a) : "l"(p));
    return a;
}
__device__ __forceinline__ void ldmx4(uint32_t* r, uint32_t addr) {
    asm volatile("ldmatrix.sync.aligned.m8n8.x4.shared.b16 {%0,%1,%2,%3}, [%4];"
        : "=r"(r[0]), "=r"(r[1]), "=r"(r[2]), "=r"(r[3]) : "r"(addr));
}
__device__ __forceinline__ void ldmx4t(uint32_t* r, uint32_t addr) {
    asm volatile("ldmatrix.sync.aligned.m8n8.x4.trans.shared.b16 {%0,%1,%2,%3}, [%4];"
        : "=r"(r[0]), "=r"(r[1]), "=r"(r[2]), "=r"(r[3]) : "r"(addr));
}
__device__ __forceinline__ void mma16816(float* d, const uint32_t* a,
                                         uint32_t b0, uint32_t b1) {
    asm volatile("mma.sync.aligned.m16n8k16.row.col.f32.f16.f16.f32 "
        "{%0,%1,%2,%3}, {%4,%5,%6,%7}, {%8,%9}, {%0,%1,%2,%3};"
        : "+f"(d[0]), "+f"(d[1]), "+f"(d[2]), "+f"(d[3])
        : "r"(a[0]), "r"(a[1]), "r"(a[2]), "r"(a[3]), "r"(b0), "r"(b1));
}
__device__ __forceinline__ void cp16(uint32_t saddr, const void* gaddr) {
    asm volatile("cp.async.cg.shared.global [%0], [%1], 16;"
        :: "r"(saddr), "l"(gaddr) : "memory");
}
#define CP_COMMIT() asm volatile("cp.async.commit_group;" ::: "memory")
#define CP_WAIT2()  asm volatile("cp.async.wait_group 2;"  ::: "memory")
#define CP_WAIT1()  asm volatile("cp.async.wait_group 1;"  ::: "memory")
#define CP_WAIT0()  asm volatile("cp.async.wait_group 0;"  ::: "memory")

__device__ __forceinline__ void splith(float v, __half& h, __half& l) {
    h = __float2half(v);
    l = __float2half(v - __half2float(h));
}
__device__ __forceinline__ uint32_t pack2h(__half a, __half b) {
    __half2 t = __halves2half2(a, b);
    return *(uint32_t*)&t;
}

// ---------------- scratch ----------------
__device__ float g_x [Mz*Dz];
__device__ __half g_h  [Mz*Dz];
__device__ __half g_qkvh[Mz*QKVN]; __device__ __half g_qkvl[Mz*QKVN];
__device__ __half g_yh [Mz*Dz];
__device__ __half g_fh [Mz*Fz];
// transposed split weights [L][N][K]
__device__ __half g_wqkvh[Lz*QKVN*Dz]; __device__ __half g_wqkvl[Lz*QKVN*Dz];
__device__ __half g_wph[Lz*Dz*Dz];     __device__ __half g_wpl[Lz*Dz*Dz];
__device__ __half g_w1h[Lz*Dz*Fz];     __device__ __half g_w1l[Lz*Dz*Fz];
__device__ __half g_w2h[Lz*Dz*Fz];     __device__ __half g_w2l[Lz*Dz*Fz];
__device__ float g_bqkv[Lz*QKVN];

// ---------------- merged weight split+transpose + bias pack ----------------
__global__ void __launch_bounds__(256) wsplit_all_kernel(
    const float* __restrict__ Wq, const float* __restrict__ Wk,
    const float* __restrict__ Wv, const float* __restrict__ Wp,
    const float* __restrict__ W1, const float* __restrict__ W2,
    const float* __restrict__ bq, const float* __restrict__ bk,
    const float* __restrict__ bv, float* __restrict__ bqkv,
    __half* __restrict__ qkvh, __half* __restrict__ qkvl,
    __half* __restrict__ ph, __half* __restrict__ pl,
    __half* __restrict__ f1h, __half* __restrict__ f1l,
    __half* __restrict__ f2h, __half* __restrict__ f2l)
{
    int idx = blockIdx.x, lyr = blockIdx.y;
    if (idx >= 6912) {
        for (int c = threadIdx.x; c < QKVN; c += 256) {
            float v = (c < Dz) ? bq[lyr*Dz + c] : (c < 2*Dz) ? bk[lyr*Dz + c - Dz]
                                                             : bv[lyr*Dz + c - 2*Dz];
            bqkv[lyr*QKVN + c] = v;
        }
        return;
    }
    const float* W; __half *hi, *lo;
    int x, y, K, N, nroff; size_t obase;
    if (idx < 2304) {
        int which = idx / 576, local = idx % 576;
        x = local % 24; y = local / 24; K = Dz; N = Dz;
        if (which < 3) {
            W = (which == 0) ? Wq : (which == 1) ? Wk : Wv;
            hi = qkvh; lo = qkvl;
            obase = (size_t)lyr * QKVN * Dz; nroff = which * Dz;
        } else {
            W = Wp; hi = ph; lo = pl;
            obase = (size_t)lyr * Dz * Dz; nroff = 0;
        }
    } else if (idx < 4608) {
        int local = idx - 2304;
        x = local % 96; y = local / 96; K = Dz; N = Fz;
        W = W1; hi = f1h; lo = f1l;
        obase = (size_t)lyr * Dz * Fz; nroff = 0;
    } else {
        int local = idx - 4608;
        x = local % 24; y = local / 24; K = Fz; N = Dz;
        W = W2; hi = f2h; lo = f2l;
        obase = (size_t)lyr * Dz * Fz; nroff = 0;
    }
    __shared__ float t[32][33];
    const float* Wl = W + (size_t)lyr * K * N;
    int k0 = y * 32, n0 = x * 32;
    int tx = threadIdx.x & 31, ty = threadIdx.x >> 5;
    #pragma unroll
    for (int i = 0; i < 4; ++i)
        t[ty + i*8][tx] = Wl[(size_t)(k0 + ty + i*8) * N + n0 + tx];
    __syncthreads();
    #pragma unroll
    for (int i = 0; i < 4; ++i) {
        int n = ty + i*8;
        float v = t[tx][n];
        __half h, l; splith(v, h, l);
        size_t o = obase + (size_t)(nroff + n0 + n) * K + k0 + tx;
        hi[o] = h; lo[o] = l;
    }
}

// ---------------- embedding ----------------
__global__ void __launch_bounds__(256) embed_kernel(
    const int* __restrict__ idx_up, const int* __restrict__ idx_down,
    const float* __restrict__ cond, const float* __restrict__ teu,
    const float* __restrict__ ted, const float* __restrict__ pos,
    const float* __restrict__ cw, const float* __restrict__ cb,
    float* __restrict__ x)
{
    int row = blockIdx.x;
    int b = row / Tz, i = row % Tz;
    int seg = i >> 9, p = i & 511;
    __shared__ float cs[NMz];
    float o[3];
    if (seg == 0) {
        for (int kk = threadIdx.x; kk < NMz; kk += 256)
            cs[kk] = cond[((size_t)(b*BS + p))*NMz + kk];
        __syncthreads();
        #pragma unroll
        for (int j = 0; j < 3; ++j) {
            int d = threadIdx.x + j*256;
            float acc = cb[d];
            for (int kk = 0; kk < NMz; ++kk)
                acc = fmaf(cs[kk], cw[kk*Dz + d], acc);
            o[j] = acc;
        }
    } else {
        int tok = (seg == 1) ? idx_up[b*BS + p] : idx_down[b*BS + p];
        const float* te = (seg == 1) ? teu : ted;
        #pragma unroll
        for (int j = 0; j < 3; ++j)
            o[j] = te[(size_t)tok*Dz + threadIdx.x + j*256];
    }
    #pragma unroll
    for (int j = 0; j < 3; ++j) {
        int d = threadIdx.x + j*256;
        x[(size_t)row*Dz + d] = o[j] + pos[(size_t)i*Dz + d];
    }
}

// ---------------- layernorm -> fp16 (hi only) ----------------
__global__ void __launch_bounds__(256) ln_kernel(
    const float* __restrict__ x, const float* __restrict__ w,
    const float* __restrict__ bb, __half* __restrict__ oh)
{
    int row = blockIdx.x;
    const float* xr = x + (size_t)row * Dz;
    int t = threadIdx.x, lane = t & 31, wid = t >> 5;
    float a0 = xr[t], a1 = xr[t+256], a2 = xr[t+512];
    float s = a0 + a1 + a2;
    __shared__ float red[8];
    #pragma unroll
    for (int off = 16; off; off >>= 1) s += __shfl_xor_sync(~0u, s, off);
    if (!lane) red[wid] = s;
    __syncthreads();
    s = red[0]+red[1]+red[2]+red[3]+red[4]+red[5]+red[6]+red[7];
    float mean = s * (1.0f/768.0f);
    float d0 = a0-mean, d1 = a1-mean, d2 = a2-mean;
    float sq = d0*d0 + d1*d1 + d2*d2;
    __syncthreads();
    #pragma unroll
    for (int off = 16; off; off >>= 1) sq += __shfl_xor_sync(~0u, sq, off);
    if (!lane) red[wid] = sq;
    __syncthreads();
    sq = red[0]+red[1]+red[2]+red[3]+red[4]+red[5]+red[6]+red[7];
    float rstd = rsqrtf(sq * (1.0f/768.0f) + 1e-5f);
    size_t ro = (size_t)row * Dz;
    oh[ro+t]     = __float2half(d0*rstd*w[t]     + bb[t]);
    oh[ro+t+256] = __float2half(d1*rstd*w[t+256] + bb[t+256]);
    oh[ro+t+512] = __float2half(d2*rstd*w[t+512] + bb[t+512]);
}

// ---------------- fp16x2 GEMM: 128x128 tile, 8 warps (2x4), 4-stage ring ----
// Hoisted loads: issue kt+2 before wait_group 2 (safe with NSTG=4 only).
// C = Ah*(Bh+Bl)^T.  epi: 0 Cf=D+b ; 1 gelu->Ch ; 2 Cf=D+b+res ; 3 split->Ch(+Cl if col>=Dz)
#define GKC 32
#define AT 8192                    // 128 rows * 64 B
#define STAGE (3*AT)               // A, Bh, Bl = 24576
#define NSTG 4
#define GSMEM (NSTG*STAGE)         // 98304
#define SWC(r, c) (((r) << 6) + ((((c) ^ (((r) & 7) >> 1))) << 4))

__global__ void __launch_bounds__(256, 2) gemm_kernel(
    const __half* __restrict__ Ah,
    const __half* __restrict__ Bh, const __half* __restrict__ Bl,
    const float* __restrict__ bias, const float* __restrict__ res,
    float* __restrict__ Cf, __half* __restrict__ Ch,
    __half* __restrict__ Cl, int K, int N, int epi)
{
    extern __shared__ char smem[];
    uint32_t sb = smem_u32(smem);
    int tid = threadIdx.x, lane = tid & 31, wid = tid >> 5;   // 8 warps
    int wm = wid & 1, wn = wid >> 1;                          // 2(M) x 4(N)
    int row0 = blockIdx.y * 128, col0 = blockIdx.x * 128;

    float acc[4][4][4];
    #pragma unroll
    for (int a = 0; a < 4; ++a)
        #pragma unroll
        for (int b = 0; b < 4; ++b)
            #pragma unroll
            for (int c = 0; c < 4; ++c) acc[a][b][c] = 0.0f;

    int lr = tid >> 2, lc = tid & 3;    // lr 0..63, chunk lc
    int grp = lane >> 3, lrow = lane & 7;
    int T = K / GKC;

    auto load_stage = [&](int stg) {
        uint32_t st = sb + (stg % NSTG) * STAGE;
        int kc0 = stg * GKC;
        const __half* a = Ah + (size_t)(row0 + lr) * K + kc0 + lc * 8;
        cp16(st + SWC(lr,      lc), a);
        cp16(st + SWC(lr + 64, lc), a + (size_t)64 * K);
        const __half* bh = Bh + (size_t)(col0 + lr) * K + kc0 + lc * 8;
        const __half* bl = Bl + (size_t)(col0 + lr) * K + kc0 + lc * 8;
        cp16(st + AT   + SWC(lr,      lc), bh);
        cp16(st + AT   + SWC(lr + 64, lc), bh + (size_t)64 * K);
        cp16(st + 2*AT + SWC(lr,      lc), bl);
        cp16(st + 2*AT + SWC(lr + 64, lc), bl + (size_t)64 * K);
    };

    load_stage(0); CP_COMMIT();
    load_stage(1); CP_COMMIT();

    for (int kt = 0; kt < T; ++kt) {
        // hoisted prefetch: slot (kt+2)%4 last held stage kt-2, fully consumed
        // before the barrier all warps passed at iteration kt-1 -> WAR-safe.
        if (kt + 2 < T) load_stage(kt + 2);
        CP_COMMIT();
        CP_WAIT2();            // group kt complete; kt+1, kt+2 may be in flight
        __syncthreads();

        uint32_t As = sb + (kt % NSTG) * STAGE;
        uint32_t Bhs = As + AT, Bls = As + 2*AT;

        #pragma unroll
        for (int ks = 0; ks < 2; ++ks) {
            uint32_t bh_[2][4], bl_[2][4];
            #pragma unroll
            for (int bi = 0; bi < 2; ++bi) {
                int n = wn*32 + bi*16 + (grp >> 1)*8 + lrow;
                int c = ks*2 + (grp & 1);
                uint32_t off = SWC(n, c);
                ldmx4(bh_[bi], Bhs + off);
                ldmx4(bl_[bi], Bls + off);
            }
            #pragma unroll
            for (int mi = 0; mi < 4; ++mi) {
                int r = wm*64 + mi*16 + (grp & 1)*8 + lrow;
                int c = ks*2 + (grp >> 1);
                uint32_t af[4];
                ldmx4(af, As + SWC(r, c));
                #pragma unroll
                for (int nj = 0; nj < 4; ++nj) {
                    uint32_t b0h = bh_[nj>>1][(nj&1)*2], b1h = bh_[nj>>1][(nj&1)*2+1];
                    uint32_t b0l = bl_[nj>>1][(nj&1)*2], b1l = bl_[nj>>1][(nj&1)*2+1];
                    mma16816(acc[mi][nj], af, b0h, b1h);
                    mma16816(acc[mi][nj], af, b0l, b1l);
                }
            }
        }
    }
    __syncthreads();

    #pragma unroll
    for (int mi = 0; mi < 4; ++mi) {
        #pragma unroll
        for (int nj = 0; nj < 4; ++nj) {
            int gr = row0 + wm*64 + mi*16 + (lane >> 2);
            int gc = col0 + wn*32 + nj*8 + (lane & 3)*2;
            float bz0 = bias[gc], bz1 = bias[gc + 1];
            #pragma unroll
            for (int half_ = 0; half_ < 2; ++half_) {
                int r = gr + half_*8;
                float v0 = acc[mi][nj][half_*2]     + bz0;
                float v1 = acc[mi][nj][half_*2 + 1] + bz1;
                size_t off = (size_t)r * N + gc;
                if (epi == 0) {
                    *(float2*)(Cf + off) = make_float2(v0, v1);
                } else if (epi == 2) {
                    float2 rv = *(const float2*)(res + off);
                    *(float2*)(Cf + off) = make_float2(v0 + rv.x, v1 + rv.y);
                } else if (epi == 1) {
                    float g0 = 0.5f*v0*(1.0f + erff(v0*0.70710678118654752f));
                    float g1 = 0.5f*v1*(1.0f + erff(v1*0.70710678118654752f));
                    *(__half2*)(Ch + off) = __halves2half2(__float2half(g0), __float2half(g1));
                } else {
                    __half h0,l0,h1,l1;
                    splith(v0,h0,l0); splith(v1,h1,l1);
                    *(__half2*)(Ch + off) = __halves2half2(h0, h1);
                    if (gc >= Dz)
                        *(__half2*)(Cl + off) = __halves2half2(l0, l1);
                }
            }
        }
    }
}

// ---------------- MMA flash attention (fp16x2), 64-query CTA, 32-key tiles --
// S = Qh*(Kh+Kl)^T ; O = Ph*(Vh+Vl)   [R13 measured-best shape]
#define SWA(r, c) (((r) << 7) + ((((c) ^ ((r) & 7))) << 4))
#define ASM_Q  0
#define ASM_KV 8192
#define ASM_TOTAL 40960

__global__ void __launch_bounds__(128) attn_kernel(
    const __half* __restrict__ QKVh, const __half* __restrict__ QKVl,
    __half* __restrict__ Yh)
{
    extern __shared__ char sm[];
    uint32_t sb = smem_u32(sm);
    int qt = blockIdx.x, h = blockIdx.y, b = blockIdx.z;
    int i0 = qt * 64;
    int p0 = i0 & 511;
    int tid = threadIdx.x, lane = tid & 31, wm = tid >> 5;

    int ntseg = (p0 >> 5) + 2;
    int NT = 3 * ntseg;
    int qoff = h * HDz, koff = Dz + h * HDz, voff = 2 * Dz + h * HDz;

    {   // stage Q (hi only)
        int rr = tid >> 1, cc0 = (tid & 1) * 4;
        const __half* qhp = QKVh + (size_t)(b*Tz + i0 + rr) * QKVN + qoff;
        #pragma unroll
        for (int c = 0; c < 4; ++c)
            cp16(sb + ASM_Q + SWA(rr, cc0 + c), qhp + (cc0 + c) * 8);
    }
    {   // stage KV tile 0
        int rr = tid >> 2, cc0 = (tid & 3) * 2;
        size_t grow = (size_t)(b*Tz + rr) * QKVN;
        uint32_t tb = sb + ASM_KV;
        #pragma unroll
        for (int c = 0; c < 2; ++c) {
            int ch = cc0 + c;
            cp16(tb +         SWA(rr, ch), QKVh + grow + koff + ch*8);
            cp16(tb + 4096  + SWA(rr, ch), QKVl + grow + koff + ch*8);
            cp16(tb + 8192  + SWA(rr, ch), QKVh + grow + voff + ch*8);
            cp16(tb + 12288 + SWA(rr, ch), QKVl + grow + voff + ch*8);
        }
        CP_COMMIT();
    }

    float m0 = -1e30f, m1 = -1e30f, l0 = 0.0f, l1 = 0.0f;
    float acc[8][4];
    #pragma unroll
    for (int i = 0; i < 8; ++i)
        #pragma unroll
        for (int j = 0; j < 4; ++j) acc[i][j] = 0.0f;

    uint32_t qhf[4][4];
    int qpos0 = p0 + wm*16 + (lane >> 2);
    int kcol2 = (lane & 3) * 2;

    for (int t = 0; t < NT; ++t) {
        int buf = t & 1;
        if (t + 1 < NT) {
            int t1 = t + 1;
            int seg1 = t1 / ntseg, kt1 = t1 % ntseg;
            int rr = tid >> 2, cc0 = (tid & 3) * 2;
            size_t grow = (size_t)(b*Tz + seg1*512 + kt1*32 + rr) * QKVN;
            uint32_t tb = sb + ASM_KV + (buf ^ 1) * 16384;
            #pragma unroll
            for (int c = 0; c < 2; ++c) {
                int ch = cc0 + c;
                cp16(tb +         SWA(rr, ch), QKVh + grow + koff + ch*8);
                cp16(tb + 4096  + SWA(rr, ch), QKVl + grow + koff + ch*8);
                cp16(tb + 8192  + SWA(rr, ch), QKVh + grow + voff + ch*8);
                cp16(tb + 12288 + SWA(rr, ch), QKVl + grow + voff + ch*8);
            }
            CP_COMMIT();
            CP_WAIT1();
        } else {
            CP_WAIT0();
        }
        __syncthreads();

        if (t == 0) {
            #pragma unroll
            for (int ks = 0; ks < 4; ++ks) {
                uint32_t qa = sb + ASM_Q + SWA(wm*16 + (lane & 15), ks*2 + (lane >> 4));
                ldmx4(qhf[ks], qa);
            }
        }

        uint32_t kb = sb + ASM_KV + buf * 16384;
        float sc[4][4];
        #pragma unroll
        for (int i = 0; i < 4; ++i)
            #pragma unroll
            for (int j = 0; j < 4; ++j) sc[i][j] = 0.0f;
        #pragma unroll
        for (int ks = 0; ks < 4; ++ks) {
            uint32_t bh_[2][4], bl_[2][4];
            #pragma unroll
            for (int bi = 0; bi < 2; ++bi) {
                int brow = bi*16 + ((lane >> 4) << 3) + (lane & 7);
                int bc   = ks*2 + ((lane >> 3) & 1);
                uint32_t ba = kb + SWA(brow, bc);
                ldmx4(bh_[bi], ba);
                ldmx4(bl_[bi], ba + 4096);
            }
            #pragma unroll
            for (int nt = 0; nt < 4; ++nt) {
                uint32_t b0h = bh_[nt>>1][(nt&1)*2], b1h = bh_[nt>>1][(nt&1)*2+1];
                uint32_t b0l = bl_[nt>>1][(nt&1)*2], b1l = bl_[nt>>1][(nt&1)*2+1];
                mma16816(sc[nt], qhf[ks], b0h, b1h);
                mma16816(sc[nt], qhf[ks], b0l, b1l);
            }
        }
        int kt = t % ntseg;
        int keybase = kt * 32;
        #pragma unroll
        for (int nt = 0; nt < 4; ++nt) {
            #pragma unroll
            for (int c = 0; c < 4; ++c) {
                int kp = keybase + nt*8 + kcol2 + (c & 1);
                int qp = (c < 2) ? qpos0 : qpos0 + 8;
                sc[nt][c] = (kp <= qp) ? sc[nt][c] * 0.125f : -1e30f;
            }
        }
        float smax0 = -1e30f, smax1 = -1e30f;
        #pragma unroll
        for (int nt = 0; nt < 4; ++nt) {
            smax0 = fmaxf(smax0, fmaxf(sc[nt][0], sc[nt][1]));
            smax1 = fmaxf(smax1, fmaxf(sc[nt][2], sc[nt][3]));
        }
        smax0 = fmaxf(smax0, __shfl_xor_sync(~0u, smax0, 1));
        smax0 = fmaxf(smax0, __shfl_xor_sync(~0u, smax0, 2));
        smax1 = fmaxf(smax1, __shfl_xor_sync(~0u, smax1, 1));
        smax1 = fmaxf(smax1, __shfl_xor_sync(~0u, smax1, 2));
        float mn0 = fmaxf(m0, smax0), mn1 = fmaxf(m1, smax1);
        float cr0 = __expf(m0 - mn0), cr1 = __expf(m1 - mn1);
        float p[4][4];
        float ps0 = 0.0f, ps1 = 0.0f;
        #pragma unroll
        for (int nt = 0; nt < 4; ++nt) {
            p[nt][0] = __expf(sc[nt][0] - mn0);
            p[nt][1] = __expf(sc[nt][1] - mn0);
            p[nt][2] = __expf(sc[nt][2] - mn1);
            p[nt][3] = __expf(sc[nt][3] - mn1);
            ps0 += p[nt][0] + p[nt][1];
            ps1 += p[nt][2] + p[nt][3];
        }
        ps0 += __shfl_xor_sync(~0u, ps0, 1);
        ps0 += __shfl_xor_sync(~0u, ps0, 2);
        ps1 += __shfl_xor_sync(~0u, ps1, 1);
        ps1 += __shfl_xor_sync(~0u, ps1, 2);
        l0 = l0 * cr0 + ps0;
        l1 = l1 * cr1 + ps1;
        #pragma unroll
        for (int nt = 0; nt < 8; ++nt) {
            acc[nt][0] *= cr0; acc[nt][1] *= cr0;
            acc[nt][2] *= cr1; acc[nt][3] *= cr1;
        }
        m0 = mn0; m1 = mn1;
        uint32_t pha[2][4];
        #pragma unroll
        for (int ks = 0; ks < 2; ++ks) {
            #pragma unroll
            for (int j = 0; j < 4; ++j) {
                int nt = ks*2 + (j >> 1);
                int c0 = (j & 1) * 2;
                int slot = (j >> 1) * 2 + (j & 1);
                pha[ks][slot] = pack2h(__float2half(p[nt][c0]), __float2half(p[nt][c0+1]));
            }
        }
        uint32_t vb = kb + 8192;
        #pragma unroll
        for (int ks = 0; ks < 2; ++ks) {
            #pragma unroll
            for (int dg = 0; dg < 4; ++dg) {
                int vrow = ks*16 + (lane & 15);
                int vc   = dg*2 + (lane >> 4);
                uint32_t va = vb + SWA(vrow, vc);
                uint32_t vbh_[4], vbl_[4];
                ldmx4t(vbh_, va);
                ldmx4t(vbl_, va + 4096);
                #pragma unroll
                for (int sub = 0; sub < 2; ++sub) {
                    int nt = dg*2 + sub;
                    mma16816(acc[nt], pha[ks], vbh_[sub*2], vbh_[sub*2+1]);
                    mma16816(acc[nt], pha[ks], vbl_[sub*2], vbl_[sub*2+1]);
                }
            }
        }
        __syncthreads();
    }

    float inv0 = 1.0f / l0, inv1 = 1.0f / l1;
    int gr0 = b*Tz + i0 + wm*16 + (lane >> 2);
    #pragma unroll
    for (int nt = 0; nt < 8; ++nt) {
        int col = h*HDz + nt*8 + kcol2;
        size_t o0 = (size_t)gr0 * Dz + col;
        size_t o1 = (size_t)(gr0 + 8) * Dz + col;
        *(__half2*)(Yh + o0) = __halves2half2(__float2half(acc[nt][0]*inv0),
                                              __float2half(acc[nt][1]*inv0));
        *(__half2*)(Yh + o1) = __halves2half2(__float2half(acc[nt][2]*inv1),
                                              __float2half(acc[nt][3]*inv1));
    }
}

// ---------------- launch ----------------
extern "C" void kernel_launch(void* const* d_in, const int* in_sizes, int n_in,
                              void* d_out, int out_size)
{
    const int*   idx_up   = (const int*)  d_in[0];
    const int*   idx_down = (const int*)  d_in[1];
    const float* cond     = (const float*)d_in[2];
    const float* teu      = (const float*)d_in[3];
    const float* ted      = (const float*)d_in[4];
    const float* pos      = (const float*)d_in[5];
    const float* cw       = (const float*)d_in[6];
    const float* cb       = (const float*)d_in[7];
    const float* ln1w     = (const float*)d_in[8];
    const float* ln1b     = (const float*)d_in[9];
    const float* ln2w     = (const float*)d_in[10];
    const float* ln2b     = (const float*)d_in[11];
    const float* Wq       = (const float*)d_in[12];
    const float* bq       = (const float*)d_in[13];
    const float* Wk       = (const float*)d_in[14];
    const float* bk       = (const float*)d_in[15];
    const float* Wv       = (const float*)d_in[16];
    const float* bv       = (const float*)d_in[17];
    const float* Wp       = (const float*)d_in[18];
    const float* bp       = (const float*)d_in[19];
    const float* W1       = (const float*)d_in[20];
    const float* b1       = (const float*)d_in[21];
    const float* W2       = (const float*)d_in[22];
    const float* b2       = (const float*)d_in[23];

    float *x, *bqkv;
    __half *hh, *yh, *fh, *qkvh, *qkvl;
    __half *wqkvh, *wqkvl, *wph, *wpl, *w1h, *w1l, *w2h, *w2l;
    cudaGetSymbolAddress((void**)&x,  g_x);
    cudaGetSymbolAddress((void**)&bqkv, g_bqkv);
    cudaGetSymbolAddress((void**)&hh, g_h);
    cudaGetSymbolAddress((void**)&yh, g_yh);
    cudaGetSymbolAddress((void**)&fh, g_fh);
    cudaGetSymbolAddress((void**)&qkvh, g_qkvh); cudaGetSymbolAddress((void**)&qkvl, g_qkvl);
    cudaGetSymbolAddress((void**)&wqkvh, g_wqkvh); cudaGetSymbolAddress((void**)&wqkvl, g_wqkvl);
    cudaGetSymbolAddress((void**)&wph, g_wph); cudaGetSymbolAddress((void**)&wpl, g_wpl);
    cudaGetSymbolAddress((void**)&w1h, g_w1h); cudaGetSymbolAddress((void**)&w1l, g_w1l);
    cudaGetSymbolAddress((void**)&w2h, g_w2h); cudaGetSymbolAddress((void**)&w2l, g_w2l);

    cudaFuncSetAttribute(gemm_kernel, cudaFuncAttributeMaxDynamicSharedMemorySize, GSMEM);
    cudaFuncSetAttribute(attn_kernel, cudaFuncAttributeMaxDynamicSharedMemorySize, ASM_TOTAL);

    wsplit_all_kernel<<<dim3(6913, Lz), 256>>>(Wq, Wk, Wv, Wp, W1, W2,
        bq, bk, bv, bqkv,
        wqkvh, wqkvl, wph, wpl, w1h, w1l, w2h, w2l);                       // 1
    embed_kernel<<<Mz, 256>>>(idx_up, idx_down, cond, teu, ted, pos, cw, cb, x); // 2

    dim3 gQKV(QKVN/128, Mz/128);   // (18, 96)
    dim3 gD(Dz/128, Mz/128);       // (6, 96)
    dim3 gF(Fz/128, Mz/128);       // (24, 96)
    size_t DD = (size_t)Dz * Dz, DF = (size_t)Dz * Fz, DQ = (size_t)QKVN * Dz;

    for (int l = 0; l < Lz; ++l) {
        ln_kernel<<<Mz, 256>>>(x, ln1w + l*Dz, ln1b + l*Dz, hh);                 // 3
        gemm_kernel<<<gQKV, 256, GSMEM>>>(hh, wqkvh + l*DQ, wqkvl + l*DQ,
            bqkv + l*QKVN, nullptr, nullptr, qkvh, qkvl, Dz, QKVN, 3);           // 4 <- ncu
        attn_kernel<<<dim3(24, Hz, Bz), 128, ASM_TOTAL>>>(qkvh, qkvl, yh);
        gemm_kernel<<<gD, 256, GSMEM>>>(yh, wph + l*DD, wpl + l*DD,
            bp + l*Dz, x, x, nullptr, nullptr, Dz, Dz, 2);
        ln_kernel<<<Mz, 256>>>(x, ln2w + l*Dz, ln2b + l*Dz, hh);
        gemm_kernel<<<gF, 256, GSMEM>>>(hh, w1h + l*DF, w1l + l*DF,
            b1 + l*Fz, nullptr, nullptr, fh, nullptr, Dz, Fz, 1);
        gemm_kernel<<<gD, 256, GSMEM>>>(fh, w2h + l*DF, w2l + l*DF,
            b2 + l*Dz, x, x, nullptr, nullptr, Fz, Dz, 2);
    }

    cudaMemcpyAsync(d_out, x, (size_t)out_size * sizeof(float),
                    cudaMemcpyDeviceToDevice, 0);
}

// round 17
// speedup vs baseline: 1.0592x; 1.0166x over previous
#include <cuda_runtime.h>
#include <cuda_fp16.h>
#include <math.h>
#include <stdint.h>

// ---------------- problem constants ----------------
#define Bz   8
#define BS   512
#define Tz   1536          // 3*BS
#define Dz   768
#define Hz   12
#define HDz  64
#define Lz   12
#define Fz   3072          // 4*D
#define NMz  438
#define Mz   (Bz*Tz)       // 12288 rows
#define QKVN 2304          // 3*Dz packed

// ---------------- helpers ----------------
__device__ __forceinline__ uint32_t smem_u32(const void* p) {
    uint32_t a;
    asm("{ .reg .u64 t; cvta.to.shared.u64 t, %1; cvt.u32.u64 %0, t; }" : "=r"(a) : "l"(p));
    return a;
}
__device__ __forceinline__ void ldmx4(uint32_t* r, uint32_t addr) {
    asm volatile("ldmatrix.sync.aligned.m8n8.x4.shared.b16 {%0,%1,%2,%3}, [%4];"
        : "=r"(r[0]), "=r"(r[1]), "=r"(r[2]), "=r"(r[3]) : "r"(addr));
}
__device__ __forceinline__ void ldmx4t(uint32_t* r, uint32_t addr) {
    asm volatile("ldmatrix.sync.aligned.m8n8.x4.trans.shared.b16 {%0,%1,%2,%3}, [%4];"
        : "=r"(r[0]), "=r"(r[1]), "=r"(r[2]), "=r"(r[3]) : "r"(addr));
}
__device__ __forceinline__ void mma16816(float* d, const uint32_t* a,
                                         uint32_t b0, uint32_t b1) {
    asm volatile("mma.sync.aligned.m16n8k16.row.col.f32.f16.f16.f32 "
        "{%0,%1,%2,%3}, {%4,%5,%6,%7}, {%8,%9}, {%0,%1,%2,%3};"
        : "+f"(d[0]), "+f"(d[1]), "+f"(d[2]), "+f"(d[3])
        : "r"(a[0]), "r"(a[1]), "r"(a[2]), "r"(a[3]), "r"(b0), "r"(b1));
}
__device__ __forceinline__ void cp16(uint32_t saddr, const void* gaddr) {
    asm volatile("cp.async.cg.shared.global [%0], [%1], 16;"
        :: "r"(saddr), "l"(gaddr) : "memory");
}
#define CP_COMMIT() asm volatile("cp.async.commit_group;" ::: "memory")
#define CP_WAIT2()  asm volatile("cp.async.wait_group 2;"  ::: "memory")
#define CP_WAIT1()  asm volatile("cp.async.wait_group 1;"  ::: "memory")
#define CP_WAIT0()  asm volatile("cp.async.wait_group 0;"  ::: "memory")

__device__ __forceinline__ void splith(float v, __half& h, __half& l) {
    h = __float2half(v);
    l = __float2half(v - __half2float(h));
}
__device__ __forceinline__ uint32_t pack2h(__half a, __half b) {
    __half2 t = __halves2half2(a, b);
    return *(uint32_t*)&t;
}

// ---------------- scratch ----------------
__device__ float g_x [Mz*Dz];
__device__ __half g_h  [Mz*Dz];
__device__ __half g_qkvh[Mz*QKVN]; __device__ __half g_qkvl[Mz*QKVN];
__device__ __half g_yh [Mz*Dz];
__device__ __half g_fh [Mz*Fz];
// transposed split weights [L][N][K]
__device__ __half g_wqkvh[Lz*QKVN*Dz]; __device__ __half g_wqkvl[Lz*QKVN*Dz];
__device__ __half g_wph[Lz*Dz*Dz];     __device__ __half g_wpl[Lz*Dz*Dz];
__device__ __half g_w1h[Lz*Dz*Fz];     __device__ __half g_w1l[Lz*Dz*Fz];
__device__ __half g_w2h[Lz*Dz*Fz];     __device__ __half g_w2l[Lz*Dz*Fz];
__device__ float g_bqkv[Lz*QKVN];

// ---------------- merged weight split+transpose + bias pack ----------------
__global__ void __launch_bounds__(256) wsplit_all_kernel(
    const float* __restrict__ Wq, const float* __restrict__ Wk,
    const float* __restrict__ Wv, const float* __restrict__ Wp,
    const float* __restrict__ W1, const float* __restrict__ W2,
    const float* __restrict__ bq, const float* __restrict__ bk,
    const float* __restrict__ bv, float* __restrict__ bqkv,
    __half* __restrict__ qkvh, __half* __restrict__ qkvl,
    __half* __restrict__ ph, __half* __restrict__ pl,
    __half* __restrict__ f1h, __half* __restrict__ f1l,
    __half* __restrict__ f2h, __half* __restrict__ f2l)
{
    int idx = blockIdx.x, lyr = blockIdx.y;
    if (idx >= 6912) {
        for (int c = threadIdx.x; c < QKVN; c += 256) {
            float v = (c < Dz) ? bq[lyr*Dz + c] : (c < 2*Dz) ? bk[lyr*Dz + c - Dz]
                                                             : bv[lyr*Dz + c - 2*Dz];
            bqkv[lyr*QKVN + c] = v;
        }
        return;
    }
    const float* W; __half *hi, *lo;
    int x, y, K, N, nroff; size_t obase;
    if (idx < 2304) {
        int which = idx / 576, local = idx % 576;
        x = local % 24; y = local / 24; K = Dz; N = Dz;
        if (which < 3) {
            W = (which == 0) ? Wq : (which == 1) ? Wk : Wv;
            hi = qkvh; lo = qkvl;
            obase = (size_t)lyr * QKVN * Dz; nroff = which * Dz;
        } else {
            W = Wp; hi = ph; lo = pl;
            obase = (size_t)lyr * Dz * Dz; nroff = 0;
        }
    } else if (idx < 4608) {
        int local = idx - 2304;
        x = local % 96; y = local / 96; K = Dz; N = Fz;
        W = W1; hi = f1h; lo = f1l;
        obase = (size_t)lyr * Dz * Fz; nroff = 0;
    } else {
        int local = idx - 4608;
        x = local % 24; y = local / 24; K = Fz; N = Dz;
        W = W2; hi = f2h; lo = f2l;
        obase = (size_t)lyr * Dz * Fz; nroff = 0;
    }
    __shared__ float t[32][33];
    const float* Wl = W + (size_t)lyr * K * N;
    int k0 = y * 32, n0 = x * 32;
    int tx = threadIdx.x & 31, ty = threadIdx.x >> 5;
    #pragma unroll
    for (int i = 0; i < 4; ++i)
        t[ty + i*8][tx] = Wl[(size_t)(k0 + ty + i*8) * N + n0 + tx];
    __syncthreads();
    #pragma unroll
    for (int i = 0; i < 4; ++i) {
        int n = ty + i*8;
        float v = t[tx][n];
        __half h, l; splith(v, h, l);
        size_t o = obase + (size_t)(nroff + n0 + n) * K + k0 + tx;
        hi[o] = h; lo[o] = l;
    }
}

// ---------------- embedding ----------------
__global__ void __launch_bounds__(256) embed_kernel(
    const int* __restrict__ idx_up, const int* __restrict__ idx_down,
    const float* __restrict__ cond, const float* __restrict__ teu,
    const float* __restrict__ ted, const float* __restrict__ pos,
    const float* __restrict__ cw, const float* __restrict__ cb,
    float* __restrict__ x)
{
    int row = blockIdx.x;
    int b = row / Tz, i = row % Tz;
    int seg = i >> 9, p = i & 511;
    __shared__ float cs[NMz];
    float o[3];
    if (seg == 0) {
        for (int kk = threadIdx.x; kk < NMz; kk += 256)
            cs[kk] = cond[((size_t)(b*BS + p))*NMz + kk];
        __syncthreads();
        #pragma unroll
        for (int j = 0; j < 3; ++j) {
            int d = threadIdx.x + j*256;
            float acc = cb[d];
            for (int kk = 0; kk < NMz; ++kk)
                acc = fmaf(cs[kk], cw[kk*Dz + d], acc);
            o[j] = acc;
        }
    } else {
        int tok = (seg == 1) ? idx_up[b*BS + p] : idx_down[b*BS + p];
        const float* te = (seg == 1) ? teu : ted;
        #pragma unroll
        for (int j = 0; j < 3; ++j)
            o[j] = te[(size_t)tok*Dz + threadIdx.x + j*256];
    }
    #pragma unroll
    for (int j = 0; j < 3; ++j) {
        int d = threadIdx.x + j*256;
        x[(size_t)row*Dz + d] = o[j] + pos[(size_t)i*Dz + d];
    }
}

// ---------------- layernorm -> fp16 (hi only) ----------------
__global__ void __launch_bounds__(256) ln_kernel(
    const float* __restrict__ x, const float* __restrict__ w,
    const float* __restrict__ bb, __half* __restrict__ oh)
{
    int row = blockIdx.x;
    const float* xr = x + (size_t)row * Dz;
    int t = threadIdx.x, lane = t & 31, wid = t >> 5;
    float a0 = xr[t], a1 = xr[t+256], a2 = xr[t+512];
    float s = a0 + a1 + a2;
    __shared__ float red[8];
    #pragma unroll
    for (int off = 16; off; off >>= 1) s += __shfl_xor_sync(~0u, s, off);
    if (!lane) red[wid] = s;
    __syncthreads();
    s = red[0]+red[1]+red[2]+red[3]+red[4]+red[5]+red[6]+red[7];
    float mean = s * (1.0f/768.0f);
    float d0 = a0-mean, d1 = a1-mean, d2 = a2-mean;
    float sq = d0*d0 + d1*d1 + d2*d2;
    __syncthreads();
    #pragma unroll
    for (int off = 16; off; off >>= 1) sq += __shfl_xor_sync(~0u, sq, off);
    if (!lane) red[wid] = sq;
    __syncthreads();
    sq = red[0]+red[1]+red[2]+red[3]+red[4]+red[5]+red[6]+red[7];
    float rstd = rsqrtf(sq * (1.0f/768.0f) + 1e-5f);
    size_t ro = (size_t)row * Dz;
    oh[ro+t]     = __float2half(d0*rstd*w[t]     + bb[t]);
    oh[ro+t+256] = __float2half(d1*rstd*w[t+256] + bb[t+256]);
    oh[ro+t+512] = __float2half(d2*rstd*w[t+512] + bb[t+512]);
}

// ---------------- fp16x2 GEMM: 128x128 tile, 8 warps (2x4), 4-stage ring ----
// Hoisted loads: issue kt+2 before wait_group 2 (safe with NSTG=4 only).
// C = Ah*(Bh+Bl)^T.  epi: 0 Cf=D+b ; 1 gelu->Ch ; 2 Cf=D+b+res ; 3 split->Ch(+Cl if col>=Dz)
#define GKC 32
#define AT 8192                    // 128 rows * 64 B
#define STAGE (3*AT)               // A, Bh, Bl = 24576
#define NSTG 4
#define GSMEM (NSTG*STAGE)         // 98304
#define SWC(r, c) (((r) << 6) + ((((c) ^ (((r) & 7) >> 1))) << 4))

__global__ void __launch_bounds__(256, 2) gemm_kernel(
    const __half* __restrict__ Ah,
    const __half* __restrict__ Bh, const __half* __restrict__ Bl,
    const float* __restrict__ bias, const float* __restrict__ res,
    float* __restrict__ Cf, __half* __restrict__ Ch,
    __half* __restrict__ Cl, int K, int N, int epi)
{
    extern __shared__ char smem[];
    uint32_t sb = smem_u32(smem);
    int tid = threadIdx.x, lane = tid & 31, wid = tid >> 5;   // 8 warps
    int wm = wid & 1, wn = wid >> 1;                          // 2(M) x 4(N)
    int row0 = blockIdx.y * 128, col0 = blockIdx.x * 128;

    float acc[4][4][4];
    #pragma unroll
    for (int a = 0; a < 4; ++a)
        #pragma unroll
        for (int b = 0; b < 4; ++b)
            #pragma unroll
            for (int c = 0; c < 4; ++c) acc[a][b][c] = 0.0f;

    int lr = tid >> 2, lc = tid & 3;    // lr 0..63, chunk lc
    int grp = lane >> 3, lrow = lane & 7;
    int T = K / GKC;

    auto load_stage = [&](int stg) {
        uint32_t st = sb + (stg % NSTG) * STAGE;
        int kc0 = stg * GKC;
        const __half* a = Ah + (size_t)(row0 + lr) * K + kc0 + lc * 8;
        cp16(st + SWC(lr,      lc), a);
        cp16(st + SWC(lr + 64, lc), a + (size_t)64 * K);
        const __half* bh = Bh + (size_t)(col0 + lr) * K + kc0 + lc * 8;
        const __half* bl = Bl + (size_t)(col0 + lr) * K + kc0 + lc * 8;
        cp16(st + AT   + SWC(lr,      lc), bh);
        cp16(st + AT   + SWC(lr + 64, lc), bh + (size_t)64 * K);
        cp16(st + 2*AT + SWC(lr,      lc), bl);
        cp16(st + 2*AT + SWC(lr + 64, lc), bl + (size_t)64 * K);
    };

    load_stage(0); CP_COMMIT();
    load_stage(1); CP_COMMIT();

    for (int kt = 0; kt < T; ++kt) {
        if (kt + 2 < T) load_stage(kt + 2);
        CP_COMMIT();
        CP_WAIT2();            // group kt complete; kt+1, kt+2 in flight
        __syncthreads();

        uint32_t As = sb + (kt % NSTG) * STAGE;
        uint32_t Bhs = As + AT, Bls = As + 2*AT;

        #pragma unroll
        for (int ks = 0; ks < 2; ++ks) {
            uint32_t bh_[2][4], bl_[2][4];
            #pragma unroll
            for (int bi = 0; bi < 2; ++bi) {
                int n = wn*32 + bi*16 + (grp >> 1)*8 + lrow;
                int c = ks*2 + (grp & 1);
                uint32_t off = SWC(n, c);
                ldmx4(bh_[bi], Bhs + off);
                ldmx4(bl_[bi], Bls + off);
            }
            #pragma unroll
            for (int mi = 0; mi < 4; ++mi) {
                int r = wm*64 + mi*16 + (grp & 1)*8 + lrow;
                int c = ks*2 + (grp >> 1);
                uint32_t af[4];
                ldmx4(af, As + SWC(r, c));
                #pragma unroll
                for (int nj = 0; nj < 4; ++nj) {
                    uint32_t b0h = bh_[nj>>1][(nj&1)*2], b1h = bh_[nj>>1][(nj&1)*2+1];
                    uint32_t b0l = bl_[nj>>1][(nj&1)*2], b1l = bl_[nj>>1][(nj&1)*2+1];
                    mma16816(acc[mi][nj], af, b0h, b1h);
                    mma16816(acc[mi][nj], af, b0l, b1l);
                }
            }
        }
    }
    __syncthreads();

    #pragma unroll
    for (int mi = 0; mi < 4; ++mi) {
        #pragma unroll
        for (int nj = 0; nj < 4; ++nj) {
            int gr = row0 + wm*64 + mi*16 + (lane >> 2);
            int gc = col0 + wn*32 + nj*8 + (lane & 3)*2;
            float bz0 = bias[gc], bz1 = bias[gc + 1];
            #pragma unroll
            for (int half_ = 0; half_ < 2; ++half_) {
                int r = gr + half_*8;
                float v0 = acc[mi][nj][half_*2]     + bz0;
                float v1 = acc[mi][nj][half_*2 + 1] + bz1;
                size_t off = (size_t)r * N + gc;
                if (epi == 0) {
                    *(float2*)(Cf + off) = make_float2(v0, v1);
                } else if (epi == 2) {
                    float2 rv = *(const float2*)(res + off);
                    *(float2*)(Cf + off) = make_float2(v0 + rv.x, v1 + rv.y);
                } else if (epi == 1) {
                    float g0 = 0.5f*v0*(1.0f + erff(v0*0.70710678118654752f));
                    float g1 = 0.5f*v1*(1.0f + erff(v1*0.70710678118654752f));
                    *(__half2*)(Ch + off) = __halves2half2(__float2half(g0), __float2half(g1));
                } else {
                    __half h0,l0,h1,l1;
                    splith(v0,h0,l0); splith(v1,h1,l1);
                    *(__half2*)(Ch + off) = __halves2half2(h0, h1);
                    if (gc >= Dz)
                        *(__half2*)(Cl + off) = __halves2half2(l0, l1);
                }
            }
        }
    }
}

// ---------------- MMA flash attention (fp16x2), 64q/32k, 3-stage hoisted ring
// S = Qh*(Kh+Kl)^T ; O = Ph*(Vh+Vl)
#define SWA(r, c) (((r) << 7) + ((((c) ^ ((r) & 7))) << 4))
#define ASM_Q   0
#define ASM_KV  8192
#define AKV_ST  16384               // kh,kl,vh,vl @ 4KB
#define ANSTG   3
#define ASM_TOTAL (ASM_KV + ANSTG*AKV_ST)   // 57344

__global__ void __launch_bounds__(128) attn_kernel(
    const __half* __restrict__ QKVh, const __half* __restrict__ QKVl,
    __half* __restrict__ Yh)
{
    extern __shared__ char sm[];
    uint32_t sb = smem_u32(sm);
    int qt = blockIdx.x, h = blockIdx.y, b = blockIdx.z;
    int i0 = qt * 64;
    int p0 = i0 & 511;
    int tid = threadIdx.x, lane = tid & 31, wm = tid >> 5;

    int ntseg = (p0 >> 5) + 2;
    int NT = 3 * ntseg;
    int qoff = h * HDz, koff = Dz + h * HDz, voff = 2 * Dz + h * HDz;

    auto load_tile = [&](int t) {
        int seg = t / ntseg, kt = t % ntseg;
        int rr = tid >> 2, cc0 = (tid & 3) * 2;
        size_t grow = (size_t)(b*Tz + seg*512 + kt*32 + rr) * QKVN;
        uint32_t tb = sb + ASM_KV + (t % ANSTG) * AKV_ST;
        #pragma unroll
        for (int c = 0; c < 2; ++c) {
            int ch = cc0 + c;
            cp16(tb +         SWA(rr, ch), QKVh + grow + koff + ch*8);
            cp16(tb + 4096  + SWA(rr, ch), QKVl + grow + koff + ch*8);
            cp16(tb + 8192  + SWA(rr, ch), QKVh + grow + voff + ch*8);
            cp16(tb + 12288 + SWA(rr, ch), QKVl + grow + voff + ch*8);
        }
    };

    {   // stage Q (hi only) with tile 0 (same cp group)
        int rr = tid >> 1, cc0 = (tid & 1) * 4;
        const __half* qhp = QKVh + (size_t)(b*Tz + i0 + rr) * QKVN + qoff;
        #pragma unroll
        for (int c = 0; c < 4; ++c)
            cp16(sb + ASM_Q + SWA(rr, cc0 + c), qhp + (cc0 + c) * 8);
    }
    load_tile(0); CP_COMMIT();
    load_tile(1); CP_COMMIT();

    float m0 = -1e30f, m1 = -1e30f, l0 = 0.0f, l1 = 0.0f;
    float acc[8][4];
    #pragma unroll
    for (int i = 0; i < 8; ++i)
        #pragma unroll
        for (int j = 0; j < 4; ++j) acc[i][j] = 0.0f;

    uint32_t qhf[4][4];
    int qpos0 = p0 + wm*16 + (lane >> 2);
    int kcol2 = (lane & 3) * 2;

    for (int t = 0; t < NT; ++t) {
        // hoisted prefetch: slot (t+2)%3 held t-1, consumed before the
        // trailing barrier of iteration t-1 that all warps passed -> WAR-safe.
        if (t + 2 < NT) load_tile(t + 2);
        CP_COMMIT();
        CP_WAIT2();            // group t complete (incl. Q on t=0)
        __syncthreads();

        if (t == 0) {
            #pragma unroll
            for (int ks = 0; ks < 4; ++ks) {
                uint32_t qa = sb + ASM_Q + SWA(wm*16 + (lane & 15), ks*2 + (lane >> 4));
                ldmx4(qhf[ks], qa);
            }
        }

        uint32_t kb = sb + ASM_KV + (t % ANSTG) * AKV_ST;
        float sc[4][4];
        #pragma unroll
        for (int i = 0; i < 4; ++i)
            #pragma unroll
            for (int j = 0; j < 4; ++j) sc[i][j] = 0.0f;
        #pragma unroll
        for (int ks = 0; ks < 4; ++ks) {
            uint32_t bh_[2][4], bl_[2][4];
            #pragma unroll
            for (int bi = 0; bi < 2; ++bi) {
                int brow = bi*16 + ((lane >> 4) << 3) + (lane & 7);
                int bc   = ks*2 + ((lane >> 3) & 1);
                uint32_t ba = kb + SWA(brow, bc);
                ldmx4(bh_[bi], ba);
                ldmx4(bl_[bi], ba + 4096);
            }
            #pragma unroll
            for (int nt = 0; nt < 4; ++nt) {
                uint32_t b0h = bh_[nt>>1][(nt&1)*2], b1h = bh_[nt>>1][(nt&1)*2+1];
                uint32_t b0l = bl_[nt>>1][(nt&1)*2], b1l = bl_[nt>>1][(nt&1)*2+1];
                mma16816(sc[nt], qhf[ks], b0h, b1h);
                mma16816(sc[nt], qhf[ks], b0l, b1l);
            }
        }
        int kt = t % ntseg;
        int keybase = kt * 32;
        #pragma unroll
        for (int nt = 0; nt < 4; ++nt) {
            #pragma unroll
            for (int c = 0; c < 4; ++c) {
                int kp = keybase + nt*8 + kcol2 + (c & 1);
                int qp = (c < 2) ? qpos0 : qpos0 + 8;
                sc[nt][c] = (kp <= qp) ? sc[nt][c] * 0.125f : -1e30f;
            }
        }
        float smax0 = -1e30f, smax1 = -1e30f;
        #pragma unroll
        for (int nt = 0; nt < 4; ++nt) {
            smax0 = fmaxf(smax0, fmaxf(sc[nt][0], sc[nt][1]));
            smax1 = fmaxf(smax1, fmaxf(sc[nt][2], sc[nt][3]));
        }
        smax0 = fmaxf(smax0, __shfl_xor_sync(~0u, smax0, 1));
        smax0 = fmaxf(smax0, __shfl_xor_sync(~0u, smax0, 2));
        smax1 = fmaxf(smax1, __shfl_xor_sync(~0u, smax1, 1));
        smax1 = fmaxf(smax1, __shfl_xor_sync(~0u, smax1, 2));
        float mn0 = fmaxf(m0, smax0), mn1 = fmaxf(m1, smax1);
        float cr0 = __expf(m0 - mn0), cr1 = __expf(m1 - mn1);
        float p[4][4];
        float ps0 = 0.0f, ps1 = 0.0f;
        #pragma unroll
        for (int nt = 0; nt < 4; ++nt) {
            p[nt][0] = __expf(sc[nt][0] - mn0);
            p[nt][1] = __expf(sc[nt][1] - mn0);
            p[nt][2] = __expf(sc[nt][2] - mn1);
            p[nt][3] = __expf(sc[nt][3] - mn1);
            ps0 += p[nt][0] + p[nt][1];
            ps1 += p[nt][2] + p[nt][3];
        }
        ps0 += __shfl_xor_sync(~0u, ps0, 1);
        ps0 += __shfl_xor_sync(~0u, ps0, 2);
        ps1 += __shfl_xor_sync(~0u, ps1, 1);
        ps1 += __shfl_xor_sync(~0u, ps1, 2);
        l0 = l0 * cr0 + ps0;
        l1 = l1 * cr1 + ps1;
        #pragma unroll
        for (int nt = 0; nt < 8; ++nt) {
            acc[nt][0] *= cr0; acc[nt][1] *= cr0;
            acc[nt][2] *= cr1; acc[nt][3] *= cr1;
        }
        m0 = mn0; m1 = mn1;
        uint32_t pha[2][4];
        #pragma unroll
        for (int ks = 0; ks < 2; ++ks) {
            #pragma unroll
            for (int j = 0; j < 4; ++j) {
                int nt = ks*2 + (j >> 1);
                int c0 = (j & 1) * 2;
                int slot = (j >> 1) * 2 + (j & 1);
                pha[ks][slot] = pack2h(__float2half(p[nt][c0]), __float2half(p[nt][c0+1]));
            }
        }
        uint32_t vb = kb + 8192;
        #pragma unroll
        for (int ks = 0; ks < 2; ++ks) {
            #pragma unroll
            for (int dg = 0; dg < 4; ++dg) {
                int vrow = ks*16 + (lane & 15);
                int vc   = dg*2 + (lane >> 4);
                uint32_t va = vb + SWA(vrow, vc);
                uint32_t vbh_[4], vbl_[4];
                ldmx4t(vbh_, va);
                ldmx4t(vbl_, va + 4096);
                #pragma unroll
                for (int sub = 0; sub < 2; ++sub) {
                    int nt = dg*2 + sub;
                    mma16816(acc[nt], pha[ks], vbh_[sub*2], vbh_[sub*2+1]);
                    mma16816(acc[nt], pha[ks], vbl_[sub*2], vbl_[sub*2+1]);
                }
            }
        }
        __syncthreads();
    }

    float inv0 = 1.0f / l0, inv1 = 1.0f / l1;
    int gr0 = b*Tz + i0 + wm*16 + (lane >> 2);
    #pragma unroll
    for (int nt = 0; nt < 8; ++nt) {
        int col = h*HDz + nt*8 + kcol2;
        size_t o0 = (size_t)gr0 * Dz + col;
        size_t o1 = (size_t)(gr0 + 8) * Dz + col;
        *(__half2*)(Yh + o0) = __halves2half2(__float2half(acc[nt][0]*inv0),
                                              __float2half(acc[nt][1]*inv0));
        *(__half2*)(Yh + o1) = __halves2half2(__float2half(acc[nt][2]*inv1),
                                              __float2half(acc[nt][3]*inv1));
    }
}

// ---------------- launch ----------------
extern "C" void kernel_launch(void* const* d_in, const int* in_sizes, int n_in,
                              void* d_out, int out_size)
{
    const int*   idx_up   = (const int*)  d_in[0];
    const int*   idx_down = (const int*)  d_in[1];
    const float* cond     = (const float*)d_in[2];
    const float* teu      = (const float*)d_in[3];
    const float* ted      = (const float*)d_in[4];
    const float* pos      = (const float*)d_in[5];
    const float* cw       = (const float*)d_in[6];
    const float* cb       = (const float*)d_in[7];
    const float* ln1w     = (const float*)d_in[8];
    const float* ln1b     = (const float*)d_in[9];
    const float* ln2w     = (const float*)d_in[10];
    const float* ln2b     = (const float*)d_in[11];
    const float* Wq       = (const float*)d_in[12];
    const float* bq       = (const float*)d_in[13];
    const float* Wk       = (const float*)d_in[14];
    const float* bk       = (const float*)d_in[15];
    const float* Wv       = (const float*)d_in[16];
    const float* bv       = (const float*)d_in[17];
    const float* Wp       = (const float*)d_in[18];
    const float* bp       = (const float*)d_in[19];
    const float* W1       = (const float*)d_in[20];
    const float* b1       = (const float*)d_in[21];
    const float* W2       = (const float*)d_in[22];
    const float* b2       = (const float*)d_in[23];

    float *x, *bqkv;
    __half *hh, *yh, *fh, *qkvh, *qkvl;
    __half *wqkvh, *wqkvl, *wph, *wpl, *w1h, *w1l, *w2h, *w2l;
    cudaGetSymbolAddress((void**)&x,  g_x);
    cudaGetSymbolAddress((void**)&bqkv, g_bqkv);
    cudaGetSymbolAddress((void**)&hh, g_h);
    cudaGetSymbolAddress((void**)&yh, g_yh);
    cudaGetSymbolAddress((void**)&fh, g_fh);
    cudaGetSymbolAddress((void**)&qkvh, g_qkvh); cudaGetSymbolAddress((void**)&qkvl, g_qkvl);
    cudaGetSymbolAddress((void**)&wqkvh, g_wqkvh); cudaGetSymbolAddress((void**)&wqkvl, g_wqkvl);
    cudaGetSymbolAddress((void**)&wph, g_wph); cudaGetSymbolAddress((void**)&wpl, g_wpl);
    cudaGetSymbolAddress((void**)&w1h, g_w1h); cudaGetSymbolAddress((void**)&w1l, g_w1l);
    cudaGetSymbolAddress((void**)&w2h, g_w2h); cudaGetSymbolAddress((void**)&w2l, g_w2l);

    cudaFuncSetAttribute(gemm_kernel, cudaFuncAttributeMaxDynamicSharedMemorySize, GSMEM);
    cudaFuncSetAttribute(attn_kernel, cudaFuncAttributeMaxDynamicSharedMemorySize, ASM_TOTAL);

    wsplit_all_kernel<<<dim3(6913, Lz), 256>>>(Wq, Wk, Wv, Wp, W1, W2,
        bq, bk, bv, bqkv,
        wqkvh, wqkvl, wph, wpl, w1h, w1l, w2h, w2l);                       // 1
    embed_kernel<<<Mz, 256>>>(idx_up, idx_down, cond, teu, ted, pos, cw, cb, x); // 2

    dim3 gQKV(QKVN/128, Mz/128);   // (18, 96)
    dim3 gD(Dz/128, Mz/128);       // (6, 96)
    dim3 gF(Fz/128, Mz/128);       // (24, 96)
    size_t DD = (size_t)Dz * Dz, DF = (size_t)Dz * Fz, DQ = (size_t)QKVN * Dz;

    for (int l = 0; l < Lz; ++l) {
        ln_kernel<<<Mz, 256>>>(x, ln1w + l*Dz, ln1b + l*Dz, hh);                 // 3
        gemm_kernel<<<gQKV, 256, GSMEM>>>(hh, wqkvh + l*DQ, wqkvl + l*DQ,
            bqkv + l*QKVN, nullptr, nullptr, qkvh, qkvl, Dz, QKVN, 3);           // 4 <- ncu
        attn_kernel<<<dim3(24, Hz, Bz), 128, ASM_TOTAL>>>(qkvh, qkvl, yh);
        gemm_kernel<<<gD, 256, GSMEM>>>(yh, wph + l*DD, wpl + l*DD,
            bp + l*Dz, x, x, nullptr, nullptr, Dz, Dz, 2);
        ln_kernel<<<Mz, 256>>>(x, ln2w + l*Dz, ln2b + l*Dz, hh);
        gemm_kernel<<<gF, 256, GSMEM>>>(hh, w1h + l*DF, w1l + l*DF,
            b1 + l*Fz, nullptr, nullptr, fh, nullptr, Dz, Fz, 1);
        gemm_kernel<<<gD, 256, GSMEM>>>(fh, w2h + l*DF, w2l + l*DF,
            b2 + l*Dz, x, x, nullptr, nullptr, Fz, Dz, 2);
    }

    cudaMemcpyAsync(d_out, x, (size_t)out_size * sizeof(float),
                    cudaMemcpyDeviceToDevice, 0);
}